// round 14
// baseline (speedup 1.0000x reference)
#include <cuda_runtime.h>
#include <cuda_fp16.h>
#include <math.h>
#include <stdint.h>

#define NN 100000
#define NE 1600000
#define NEG_SLOPE 0.2f
#define NB_SETUP 98   // ceil(NN/1024)
#define CAP 128       // bucket capacity per dst (P(deg>=128) ~ 1e-55)
#define LOG2E 1.44269504f

#define XS_STRIDE 132
#define WS_STRIDE 136
#define XS2_STRIDE 132
#define WS2_STRIDE 36

// ---------------- scratch (device globals; no allocations allowed) ----------
__device__ float  g_h[NN * 2];       // layer-3 h (f32, tiny)
__device__ __half g_h16[NN * 128];   // fp16 messages for layers 1/2
__device__ float  g_agg[NN * 128];   // layer-1 output (ELU'd) -> layer-2 input
__device__ float  g_agg2[NN * 32];   // layer-2 output (ELU'd) -> layer-3 input
__device__ float  g_asrc[NN * 4];
__device__ float  g_adst[NN * 4];
__device__ float  g_gm1[8];          // [0..3]=max asrc per head, [4..7]=max adst
__device__ float  g_gm2[4];          // [s0,s1,d0,d1]
__device__ float  g_gm3[2];          // [s,d]
__device__ int    g_eb[(size_t)NN * CAP];  // bucketed src ids per dst
__device__ int    g_cnt[NN];
__device__ int    g_is64;

// ---------------- helpers ---------------------------------------------------
__device__ __forceinline__ void atomicMaxF(float* a, float v) {
    if (v >= 0.f) atomicMax((int*)a, __float_as_int(v));
    else          atomicMin((unsigned int*)a, __float_as_uint(v));
}
__device__ __forceinline__ float lrelu(float v) { return v > 0.f ? v : NEG_SLOPE * v; }
__device__ __forceinline__ float lrelu_b(float v) {
    return fmaxf(v, 0.f) + NEG_SLOPE * fminf(v, 0.f);
}
__device__ __forceinline__ float eexp(float lr, float nmm) {
    return exp2f(fmaf(lr, LOG2E, nmm));
}
__device__ __forceinline__ uint32_t f2tf32(float f) {
    uint32_t r;
    asm("cvt.rna.tf32.f32 %0, %1;" : "=r"(r) : "f"(f));
    return r;
}
__device__ __forceinline__ void mma_tf32(float4& d,
                                         uint32_t a0, uint32_t a1, uint32_t a2, uint32_t a3,
                                         uint32_t b0, uint32_t b1) {
    asm("mma.sync.aligned.m16n8k8.row.col.f32.tf32.tf32.f32 "
        "{%0,%1,%2,%3}, {%4,%5,%6,%7}, {%8,%9}, {%0,%1,%2,%3};"
        : "+f"(d.x), "+f"(d.y), "+f"(d.z), "+f"(d.w)
        : "r"(a0), "r"(a1), "r"(a2), "r"(a3), "r"(b0), "r"(b1));
}
__device__ __forceinline__ float4 cvt4(uint2 u) {
    float2 a = __half22float2(*(__half2*)&u.x);
    float2 b = __half22float2(*(__half2*)&u.y);
    return make_float4(a.x, a.y, b.x, b.y);
}

// ---------------- stage 0: detect dtype, zero counts, reset maxima ----------
__global__ void k_setup(const int* __restrict__ w) {
    int i = blockIdx.x * blockDim.x + threadIdx.x;
    if (i < NN) g_cnt[i] = 0;
    if (i == 0) {
        int any = 0;
        for (int k = 0; k < 128; k++) any |= w[2 * k + 1];
        g_is64 = (any == 0) ? 1 : 0;
        for (int k = 0; k < 8; k++) g_gm1[k] = -INFINITY;
        for (int k = 0; k < 4; k++) g_gm2[k] = -INFINITY;
        g_gm3[0] = -INFINITY; g_gm3[1] = -INFINITY;
    }
}

// scatter src ids into per-dst buckets (counts + payload in one pass)
__global__ void k_scatter(const int* __restrict__ w) {
    int base = (blockIdx.x * blockDim.x + threadIdx.x) * 8;
    int is64 = g_is64;
#pragma unroll
    for (int k = 0; k < 8; k++) {
        int i = base + k;
        if (i < NE) {
            int s = is64 ? w[2 * i] : w[i];
            int d = is64 ? w[2 * (NE + i)] : w[NE + i];
            int p = atomicAdd(&g_cnt[d], 1);
            if (p < CAP) g_eb[(size_t)d * CAP + p] = s;
        }
    }
}

// ---------------- GEMM 1 via tf32 mma.sync + att dots + fused gmax ----------
__global__ void __launch_bounds__(256) k_gemm1_mma(
        const float* __restrict__ X, const float* __restrict__ W,
        const float* __restrict__ as, const float* __restrict__ ad) {
    extern __shared__ uint32_t sm[];
    uint32_t* xs = sm;                  // [64][XS_STRIDE]
    uint32_t* ws = sm + 64 * XS_STRIDE; // [128][WS_STRIDE]
    __shared__ float sgm[8];
    int t = threadIdx.x;
    if (t < 8) sgm[t] = -INFINITY;
    int row0 = blockIdx.x * 64;

    const float4* Xv = (const float4*)X;
#pragma unroll
    for (int i = 0; i < 8; i++) {
        int idx = t + i * 256;
        int row = idx >> 5, cv = idx & 31;
        float4 xv = (row0 + row < NN) ? Xv[(size_t)(row0 + row) * 32 + cv]
                                      : make_float4(0.f, 0.f, 0.f, 0.f);
        uint32_t* p = &xs[row * XS_STRIDE + cv * 4];
        p[0] = f2tf32(xv.x); p[1] = f2tf32(xv.y);
        p[2] = f2tf32(xv.z); p[3] = f2tf32(xv.w);
    }
    const float4* Wv = (const float4*)W;
#pragma unroll
    for (int i = 0; i < 16; i++) {
        int idx = t + i * 256;
        int k = idx >> 5, nv = idx & 31;
        float4 wv = Wv[idx];
        uint32_t* p = &ws[k * WS_STRIDE + nv * 4];
        p[0] = f2tf32(wv.x); p[1] = f2tf32(wv.y);
        p[2] = f2tf32(wv.z); p[3] = f2tf32(wv.w);
    }
    __syncthreads();

    int w = t >> 5, lane = t & 31;
    int r0w = (w >> 1) * 16;
    int c0 = (w & 1) * 64;
    int g = lane >> 2, tg = lane & 3;

    float4 acc[8];
#pragma unroll
    for (int i = 0; i < 8; i++) acc[i] = make_float4(0.f, 0.f, 0.f, 0.f);

#pragma unroll
    for (int kt = 0; kt < 16; kt++) {
        int k0 = kt * 8;
        uint32_t a0 = xs[(r0w + g) * XS_STRIDE + k0 + tg];
        uint32_t a1 = xs[(r0w + g + 8) * XS_STRIDE + k0 + tg];
        uint32_t a2 = xs[(r0w + g) * XS_STRIDE + k0 + tg + 4];
        uint32_t a3 = xs[(r0w + g + 8) * XS_STRIDE + k0 + tg + 4];
#pragma unroll
        for (int ti = 0; ti < 8; ti++) {
            int n0 = c0 + ti * 8 + g;
            uint32_t b0 = ws[(k0 + tg) * WS_STRIDE + n0];
            uint32_t b1 = ws[(k0 + tg + 4) * WS_STRIDE + n0];
            mma_tf32(acc[ti], a0, a1, a2, a3, b0, b1);
        }
    }

    int grow_l = row0 + r0w + g;
    int grow_h = grow_l + 8;
    int hb = c0 >> 5;   // head base for this warp (0 or 2)
    float psl[2] = {0.f, 0.f}, pdl[2] = {0.f, 0.f};
    float psh[2] = {0.f, 0.f}, pdh[2] = {0.f, 0.f};
#pragma unroll
    for (int ti = 0; ti < 8; ti++) {
        int gc = c0 + ti * 8 + tg * 2;
        float s0 = __ldg(&as[gc]), s1 = __ldg(&as[gc + 1]);
        float d0 = __ldg(&ad[gc]), d1 = __ldg(&ad[gc + 1]);
        int hi = ti >> 2;
        psl[hi] += acc[ti].x * s0 + acc[ti].y * s1;
        pdl[hi] += acc[ti].x * d0 + acc[ti].y * d1;
        psh[hi] += acc[ti].z * s0 + acc[ti].w * s1;
        pdh[hi] += acc[ti].z * d0 + acc[ti].w * d1;
        if (grow_l < NN)
            *(__half2*)&g_h16[(size_t)grow_l * 128 + gc] =
                __float22half2_rn(make_float2(acc[ti].x, acc[ti].y));
        if (grow_h < NN)
            *(__half2*)&g_h16[(size_t)grow_h * 128 + gc] =
                __float22half2_rn(make_float2(acc[ti].z, acc[ti].w));
    }
#pragma unroll
    for (int off = 1; off <= 2; off <<= 1) {
#pragma unroll
        for (int i = 0; i < 2; i++) {
            psl[i] += __shfl_xor_sync(0xffffffffu, psl[i], off);
            pdl[i] += __shfl_xor_sync(0xffffffffu, pdl[i], off);
            psh[i] += __shfl_xor_sync(0xffffffffu, psh[i], off);
            pdh[i] += __shfl_xor_sync(0xffffffffu, pdh[i], off);
        }
    }
    if (tg == 0) {
        if (grow_l < NN) {
            g_asrc[grow_l * 4 + hb]     = psl[0];
            g_asrc[grow_l * 4 + hb + 1] = psl[1];
            g_adst[grow_l * 4 + hb]     = pdl[0];
            g_adst[grow_l * 4 + hb + 1] = pdl[1];
        }
        if (grow_h < NN) {
            g_asrc[grow_h * 4 + hb]     = psh[0];
            g_asrc[grow_h * 4 + hb + 1] = psh[1];
            g_adst[grow_h * 4 + hb]     = pdh[0];
            g_adst[grow_h * 4 + hb + 1] = pdh[1];
        }
    }
    float ms[2], md[2];
#pragma unroll
    for (int i = 0; i < 2; i++) {
        float al = (grow_l < NN) ? psl[i] : -INFINITY;
        float ah = (grow_h < NN) ? psh[i] : -INFINITY;
        ms[i] = fmaxf(al, ah);
        float bl = (grow_l < NN) ? pdl[i] : -INFINITY;
        float bh = (grow_h < NN) ? pdh[i] : -INFINITY;
        md[i] = fmaxf(bl, bh);
    }
#pragma unroll
    for (int off = 4; off <= 16; off <<= 1)
#pragma unroll
        for (int i = 0; i < 2; i++) {
            ms[i] = fmaxf(ms[i], __shfl_xor_sync(0xffffffffu, ms[i], off));
            md[i] = fmaxf(md[i], __shfl_xor_sync(0xffffffffu, md[i], off));
        }
    if (lane == 0) {
#pragma unroll
        for (int i = 0; i < 2; i++) {
            atomicMaxF(&sgm[hb + i], ms[i]);
            atomicMaxF(&sgm[4 + hb + i], md[i]);
        }
    }
    __syncthreads();
    if (t < 8) atomicMaxF(&g_gm1[t], sgm[t]);
}

// ---------------- GEMM 2 via tf32 mma.sync + att dots + fused gmax ----------
__global__ void __launch_bounds__(256) k_gemm2_mma(
        const float* __restrict__ X, const float* __restrict__ W,
        const float* __restrict__ as, const float* __restrict__ ad) {
    extern __shared__ uint32_t sm2[];
    uint32_t* xs = sm2;                     // [128][XS2_STRIDE]
    uint32_t* ws = sm2 + 128 * XS2_STRIDE;  // [128][WS2_STRIDE]
    __shared__ float sgm[4];
    int t = threadIdx.x;
    if (t < 4) sgm[t] = -INFINITY;
    int row0 = blockIdx.x * 128;

    const float4* Xv = (const float4*)X;
#pragma unroll
    for (int i = 0; i < 16; i++) {
        int idx = t + i * 256;
        int row = idx >> 5, cv = idx & 31;
        float4 xv = (row0 + row < NN) ? Xv[(size_t)(row0 + row) * 32 + cv]
                                      : make_float4(0.f, 0.f, 0.f, 0.f);
        uint32_t* p = &xs[row * XS2_STRIDE + cv * 4];
        p[0] = f2tf32(xv.x); p[1] = f2tf32(xv.y);
        p[2] = f2tf32(xv.z); p[3] = f2tf32(xv.w);
    }
    const float4* Wv = (const float4*)W;
#pragma unroll
    for (int i = 0; i < 4; i++) {
        int idx = t + i * 256;
        int k = idx >> 3, nv = idx & 7;
        float4 wv = Wv[idx];
        uint32_t* p = &ws[k * WS2_STRIDE + nv * 4];
        p[0] = f2tf32(wv.x); p[1] = f2tf32(wv.y);
        p[2] = f2tf32(wv.z); p[3] = f2tf32(wv.w);
    }
    __syncthreads();

    int w = t >> 5, lane = t & 31;
    int r0w = w * 16;
    int g = lane >> 2, tg = lane & 3;

    float4 acc[4];
#pragma unroll
    for (int i = 0; i < 4; i++) acc[i] = make_float4(0.f, 0.f, 0.f, 0.f);

#pragma unroll
    for (int kt = 0; kt < 16; kt++) {
        int k0 = kt * 8;
        uint32_t a0 = xs[(r0w + g) * XS2_STRIDE + k0 + tg];
        uint32_t a1 = xs[(r0w + g + 8) * XS2_STRIDE + k0 + tg];
        uint32_t a2 = xs[(r0w + g) * XS2_STRIDE + k0 + tg + 4];
        uint32_t a3 = xs[(r0w + g + 8) * XS2_STRIDE + k0 + tg + 4];
#pragma unroll
        for (int ti = 0; ti < 4; ti++) {
            int n0 = ti * 8 + g;
            uint32_t b0 = ws[(k0 + tg) * WS2_STRIDE + n0];
            uint32_t b1 = ws[(k0 + tg + 4) * WS2_STRIDE + n0];
            mma_tf32(acc[ti], a0, a1, a2, a3, b0, b1);
        }
    }

    int grow_l = row0 + r0w + g;
    int grow_h = grow_l + 8;
    float psl[2] = {0.f, 0.f}, pdl[2] = {0.f, 0.f};
    float psh[2] = {0.f, 0.f}, pdh[2] = {0.f, 0.f};
#pragma unroll
    for (int ti = 0; ti < 4; ti++) {
        int gc = ti * 8 + tg * 2;
        float s0 = __ldg(&as[gc]), s1 = __ldg(&as[gc + 1]);
        float d0 = __ldg(&ad[gc]), d1 = __ldg(&ad[gc + 1]);
        int hi = ti >> 1;
        psl[hi] += acc[ti].x * s0 + acc[ti].y * s1;
        pdl[hi] += acc[ti].x * d0 + acc[ti].y * d1;
        psh[hi] += acc[ti].z * s0 + acc[ti].w * s1;
        pdh[hi] += acc[ti].z * d0 + acc[ti].w * d1;
        if (grow_l < NN)
            *(__half2*)&g_h16[(size_t)grow_l * 32 + gc] =
                __float22half2_rn(make_float2(acc[ti].x, acc[ti].y));
        if (grow_h < NN)
            *(__half2*)&g_h16[(size_t)grow_h * 32 + gc] =
                __float22half2_rn(make_float2(acc[ti].z, acc[ti].w));
    }
#pragma unroll
    for (int off = 1; off <= 2; off <<= 1) {
#pragma unroll
        for (int i = 0; i < 2; i++) {
            psl[i] += __shfl_xor_sync(0xffffffffu, psl[i], off);
            pdl[i] += __shfl_xor_sync(0xffffffffu, pdl[i], off);
            psh[i] += __shfl_xor_sync(0xffffffffu, psh[i], off);
            pdh[i] += __shfl_xor_sync(0xffffffffu, pdh[i], off);
        }
    }
    if (tg == 0) {
        if (grow_l < NN) {
            g_asrc[grow_l * 2]     = psl[0];
            g_asrc[grow_l * 2 + 1] = psl[1];
            g_adst[grow_l * 2]     = pdl[0];
            g_adst[grow_l * 2 + 1] = pdl[1];
        }
        if (grow_h < NN) {
            g_asrc[grow_h * 2]     = psh[0];
            g_asrc[grow_h * 2 + 1] = psh[1];
            g_adst[grow_h * 2]     = pdh[0];
            g_adst[grow_h * 2 + 1] = pdh[1];
        }
    }
    float ms[2], md[2];
#pragma unroll
    for (int i = 0; i < 2; i++) {
        float al = (grow_l < NN) ? psl[i] : -INFINITY;
        float ah = (grow_h < NN) ? psh[i] : -INFINITY;
        ms[i] = fmaxf(al, ah);
        float bl = (grow_l < NN) ? pdl[i] : -INFINITY;
        float bh = (grow_h < NN) ? pdh[i] : -INFINITY;
        md[i] = fmaxf(bl, bh);
    }
#pragma unroll
    for (int off = 4; off <= 16; off <<= 1)
#pragma unroll
        for (int i = 0; i < 2; i++) {
            ms[i] = fmaxf(ms[i], __shfl_xor_sync(0xffffffffu, ms[i], off));
            md[i] = fmaxf(md[i], __shfl_xor_sync(0xffffffffu, md[i], off));
        }
    if (lane == 0) {
#pragma unroll
        for (int i = 0; i < 2; i++) {
            atomicMaxF(&sgm[i], ms[i]);
            atomicMaxF(&sgm[2 + i], md[i]);
        }
    }
    __syncthreads();
    if (t < 4) atomicMaxF(&g_gm2[t], sgm[t]);
}

// ---------------- layer 3 GEMM + att dots + fused gmax ----------------------
__global__ void k_gemm3(const float* __restrict__ X, const float* __restrict__ W,
                        const float* __restrict__ as, const float* __restrict__ ad) {
    __shared__ float sgm[2];
    int t = threadIdx.x;
    if (t < 2) sgm[t] = -INFINITY;
    __syncthreads();
    int n = blockIdx.x * blockDim.x + t;
    float asv = -INFINITY, adv = -INFINITY;
    if (n < NN) {
        float h0 = 0.f, h1 = 0.f;
#pragma unroll
        for (int k = 0; k < 32; k++) {
            float xv = X[n * 32 + k];
            h0 += xv * W[2 * k]; h1 += xv * W[2 * k + 1];
        }
        g_h[2 * n] = h0; g_h[2 * n + 1] = h1;
        asv = h0 * as[0] + h1 * as[1];
        adv = h0 * ad[0] + h1 * ad[1];
        g_asrc[n] = asv; g_adst[n] = adv;
    }
    float ms = asv, md = adv;
#pragma unroll
    for (int off = 16; off >= 1; off >>= 1) {
        ms = fmaxf(ms, __shfl_xor_sync(0xffffffffu, ms, off));
        md = fmaxf(md, __shfl_xor_sync(0xffffffffu, md, off));
    }
    if ((t & 31) == 0) { atomicMaxF(&sgm[0], ms); atomicMaxF(&sgm[1], md); }
    __syncthreads();
    if (t < 2) atomicMaxF(&g_gm3[t], sgm[t]);
}

// ---------------- bucket aggregation ----------------------------------------
// Layer 1: F=128, H=4. One warp per dst node, two-phase.
// Phase 1: lanes stride bucket slots; per-edge 4-head exps computed ONCE,
//          packed as half2(e,e), stored transposed; per-head denominators
//          accumulated in f32 + warp-reduced here.
// Phase 2: lane owns 4 features; inner math is HFMA2 on fp16 pairs with
//          f32 flush every 8 edges (bounds fp16 accumulation error).
__global__ void __launch_bounds__(256) k_agg1(const float* __restrict__ b) {
    __shared__ __half2 sew[8][4 * CAP];   // 16 KB: per-warp packed edge weights
    int wid = threadIdx.x >> 5, lane = threadIdx.x & 31;
    int n = blockIdx.x * 8 + wid;
    if (n >= NN) return;
    __half2* sew_w = sew[wid];

    float4 gs = *(const float4*)&g_gm1[0];
    float4 gd = *(const float4*)&g_gm1[4];
    float nm0 = -lrelu_b(gs.x + gd.x) * LOG2E;
    float nm1 = -lrelu_b(gs.y + gd.y) * LOG2E;
    float nm2 = -lrelu_b(gs.z + gd.z) * LOG2E;
    float nm3 = -lrelu_b(gs.w + gd.w) * LOG2E;
    float4 ad4 = *(const float4*)&g_adst[n * 4];

    const int* eb = &g_eb[(size_t)n * CAP];
    int cnt = min(g_cnt[n], CAP);

    // phase 1: per-edge weights (once) + per-head denominator partials
    float d0 = 0.f, d1 = 0.f, d2 = 0.f, d3 = 0.f;
    for (int j = lane; j < cnt; j += 32) {
        int s = __ldg(&eb[j]);
        float4 a4 = *(const float4*)&g_asrc[s * 4];
        float e0 = eexp(lrelu_b(a4.x + ad4.x), nm0);
        float e1 = eexp(lrelu_b(a4.y + ad4.y), nm1);
        float e2 = eexp(lrelu_b(a4.z + ad4.z), nm2);
        float e3 = eexp(lrelu_b(a4.w + ad4.w), nm3);
        sew_w[j]           = __float2half2_rn(e0);
        sew_w[CAP + j]     = __float2half2_rn(e1);
        sew_w[2 * CAP + j] = __float2half2_rn(e2);
        sew_w[3 * CAP + j] = __float2half2_rn(e3);
        d0 += e0; d1 += e1; d2 += e2; d3 += e3;
    }
#pragma unroll
    for (int off = 16; off >= 1; off >>= 1) {
        d0 += __shfl_xor_sync(0xffffffffu, d0, off);
        d1 += __shfl_xor_sync(0xffffffffu, d1, off);
        d2 += __shfl_xor_sync(0xffffffffu, d2, off);
        d3 += __shfl_xor_sync(0xffffffffu, d3, off);
    }
    __syncwarp();

    // phase 2: feature accumulation (HFMA2 + chunked f32 flush)
    int h = lane >> 3, c0 = lane * 4;
    float ta = (h & 2) ? nm2 : nm0;
    float tb = (h & 2) ? nm3 : nm1;
    float nmm = (h & 1) ? tb : ta;
    float da = (h & 2) ? d2 : d0;
    float db = (h & 2) ? d3 : d1;
    float dh = (h & 1) ? db : da;
    float adn = g_adst[n * 4 + h];
    float es = eexp(lrelu_b(g_asrc[n * 4 + h] + adn), nmm);
    float4 hv = cvt4(*(const uint2*)&g_h16[(size_t)n * 128 + c0]);
    float ax = hv.x * es, ay = hv.y * es, az = hv.z * es, aw = hv.w * es;
    float den = dh + es;
    const __half2* ep = sew_w + h * CAP;
    const __half2 hzero = __float2half2_rn(0.f);
    int j = 0;
    for (; j + 8 <= cnt; j += 8) {
        int4 sA = *(const int4*)(eb + j);
        int4 sB = *(const int4*)(eb + j + 4);
        uint4 wv0 = *(const uint4*)&ep[j];       // 4 half2 weights
        uint4 wv1 = *(const uint4*)&ep[j + 4];
        uint2 u0 = *(const uint2*)&g_h16[(size_t)sA.x * 128 + c0];
        uint2 u1 = *(const uint2*)&g_h16[(size_t)sA.y * 128 + c0];
        uint2 u2 = *(const uint2*)&g_h16[(size_t)sA.z * 128 + c0];
        uint2 u3 = *(const uint2*)&g_h16[(size_t)sA.w * 128 + c0];
        uint2 u4 = *(const uint2*)&g_h16[(size_t)sB.x * 128 + c0];
        uint2 u5 = *(const uint2*)&g_h16[(size_t)sB.y * 128 + c0];
        uint2 u6 = *(const uint2*)&g_h16[(size_t)sB.z * 128 + c0];
        uint2 u7 = *(const uint2*)&g_h16[(size_t)sB.w * 128 + c0];
        __half2 acl = hzero, ach = hzero;
        acl = __hfma2(*(__half2*)&u0.x, *(__half2*)&wv0.x, acl);
        ach = __hfma2(*(__half2*)&u0.y, *(__half2*)&wv0.x, ach);
        acl = __hfma2(*(__half2*)&u1.x, *(__half2*)&wv0.y, acl);
        ach = __hfma2(*(__half2*)&u1.y, *(__half2*)&wv0.y, ach);
        acl = __hfma2(*(__half2*)&u2.x, *(__half2*)&wv0.z, acl);
        ach = __hfma2(*(__half2*)&u2.y, *(__half2*)&wv0.z, ach);
        acl = __hfma2(*(__half2*)&u3.x, *(__half2*)&wv0.w, acl);
        ach = __hfma2(*(__half2*)&u3.y, *(__half2*)&wv0.w, ach);
        acl = __hfma2(*(__half2*)&u4.x, *(__half2*)&wv1.x, acl);
        ach = __hfma2(*(__half2*)&u4.y, *(__half2*)&wv1.x, ach);
        acl = __hfma2(*(__half2*)&u5.x, *(__half2*)&wv1.y, acl);
        ach = __hfma2(*(__half2*)&u5.y, *(__half2*)&wv1.y, ach);
        acl = __hfma2(*(__half2*)&u6.x, *(__half2*)&wv1.z, acl);
        ach = __hfma2(*(__half2*)&u6.y, *(__half2*)&wv1.z, ach);
        acl = __hfma2(*(__half2*)&u7.x, *(__half2*)&wv1.w, acl);
        ach = __hfma2(*(__half2*)&u7.y, *(__half2*)&wv1.w, ach);
        float2 fl = __half22float2(acl);
        float2 fh = __half22float2(ach);
        ax += fl.x; ay += fl.y; az += fh.x; aw += fh.y;
    }
    for (; j < cnt; j++) {
        int s0 = eb[j];
        float e0 = __low2float(ep[j]);
        float4 h0 = cvt4(*(const uint2*)&g_h16[(size_t)s0 * 128 + c0]);
        ax += h0.x * e0; ay += h0.y * e0; az += h0.z * e0; aw += h0.w * e0;
    }
    float inv = __frcp_rn(den);
    float4 bv = *(const float4*)&b[c0];
    float vx = ax * inv + bv.x, vy = ay * inv + bv.y;
    float vz = az * inv + bv.z, vw = aw * inv + bv.w;
    vx = vx > 0.f ? vx : expm1f(vx);
    vy = vy > 0.f ? vy : expm1f(vy);
    vz = vz > 0.f ? vz : expm1f(vz);
    vw = vw > 0.f ? vw : expm1f(vw);
    *(float4*)&g_agg[(size_t)n * 128 + c0] = make_float4(vx, vy, vz, vw);
}

// Layer 2: F=32, H=2. 8 lanes per dst node (round-10 proven form).
__global__ void __launch_bounds__(256) k_agg2(const float* __restrict__ b) {
    int gi = blockIdx.x * blockDim.x + threadIdx.x;
    int n = gi >> 3, jl = gi & 7;
    if (n >= NN) return;
    int h = jl >> 2, c0 = jl * 4;
    float m = lrelu(g_gm2[h] + g_gm2[2 + h]);
    float nmm = -m * LOG2E;
    float adn = g_adst[n * 2 + h];
    float es = eexp(lrelu_b(g_asrc[n * 2 + h] + adn), nmm);
    float4 hv = cvt4(*(const uint2*)&g_h16[n * 32 + c0]);
    float ax = hv.x * es, ay = hv.y * es, az = hv.z * es, aw = hv.w * es;
    float den = es;
    const int* eb = &g_eb[(size_t)n * CAP];
    int cnt = min(g_cnt[n], CAP);
    int j = 0;
    for (; j + 4 <= cnt; j += 4) {
        int4 s4 = *(const int4*)(eb + j);
        float a0 = g_asrc[s4.x * 2 + h];
        float a1 = g_asrc[s4.y * 2 + h];
        float a2 = g_asrc[s4.z * 2 + h];
        float a3 = g_asrc[s4.w * 2 + h];
        uint2 u0 = *(const uint2*)&g_h16[s4.x * 32 + c0];
        uint2 u1 = *(const uint2*)&g_h16[s4.y * 32 + c0];
        uint2 u2 = *(const uint2*)&g_h16[s4.z * 32 + c0];
        uint2 u3 = *(const uint2*)&g_h16[s4.w * 32 + c0];
        float e0 = eexp(lrelu_b(a0 + adn), nmm);
        float e1 = eexp(lrelu_b(a1 + adn), nmm);
        float e2 = eexp(lrelu_b(a2 + adn), nmm);
        float e3 = eexp(lrelu_b(a3 + adn), nmm);
        float4 h0 = cvt4(u0), h1 = cvt4(u1), h2 = cvt4(u2), h3 = cvt4(u3);
        ax += h0.x * e0 + h1.x * e1 + h2.x * e2 + h3.x * e3;
        ay += h0.y * e0 + h1.y * e1 + h2.y * e2 + h3.y * e3;
        az += h0.z * e0 + h1.z * e1 + h2.z * e2 + h3.z * e3;
        aw += h0.w * e0 + h1.w * e1 + h2.w * e2 + h3.w * e3;
        den += (e0 + e1) + (e2 + e3);
    }
    for (; j < cnt; j++) {
        int s0 = eb[j];
        float a0 = g_asrc[s0 * 2 + h];
        uint2 u0 = *(const uint2*)&g_h16[s0 * 32 + c0];
        float e0 = eexp(lrelu_b(a0 + adn), nmm);
        float4 h0 = cvt4(u0);
        ax += h0.x * e0; ay += h0.y * e0; az += h0.z * e0; aw += h0.w * e0;
        den += e0;
    }
    float inv = __frcp_rn(den);
    float4 bv = *(const float4*)&b[c0];
    float vx = ax * inv + bv.x, vy = ay * inv + bv.y;
    float vz = az * inv + bv.z, vw = aw * inv + bv.w;
    vx = vx > 0.f ? vx : expm1f(vx);
    vy = vy > 0.f ? vy : expm1f(vy);
    vz = vz > 0.f ? vz : expm1f(vz);
    vw = vw > 0.f ? vw : expm1f(vw);
    *(float4*)&g_agg2[n * 32 + c0] = make_float4(vx, vy, vz, vw);
}

// Layer 3: F=2, H=1. One thread per dst node + fused log-softmax.
__global__ void k_agg3(const float* __restrict__ b3, float* __restrict__ out) {
    int n = blockIdx.x * blockDim.x + threadIdx.x;
    if (n >= NN) return;
    float m = lrelu(g_gm3[0] + g_gm3[1]);
    float nmm = -m * LOG2E;
    float adn = g_adst[n];
    float es = eexp(lrelu_b(g_asrc[n] + adn), nmm);
    float2 hv = *(const float2*)&g_h[2 * n];
    float a0 = hv.x * es, a1 = hv.y * es, den = es;
    const int* eb = &g_eb[(size_t)n * CAP];
    int cnt = min(g_cnt[n], CAP);
    int j = 0;
    for (; j + 4 <= cnt; j += 4) {
        int4 s4 = *(const int4*)(eb + j);
        float t0 = g_asrc[s4.x], t1 = g_asrc[s4.y];
        float t2 = g_asrc[s4.z], t3 = g_asrc[s4.w];
        float2 h0 = *(const float2*)&g_h[2 * s4.x];
        float2 h1 = *(const float2*)&g_h[2 * s4.y];
        float2 h2 = *(const float2*)&g_h[2 * s4.z];
        float2 h3 = *(const float2*)&g_h[2 * s4.w];
        float e0 = eexp(lrelu_b(t0 + adn), nmm);
        float e1 = eexp(lrelu_b(t1 + adn), nmm);
        float e2 = eexp(lrelu_b(t2 + adn), nmm);
        float e3 = eexp(lrelu_b(t3 + adn), nmm);
        a0 += h0.x * e0 + h1.x * e1 + h2.x * e2 + h3.x * e3;
        a1 += h0.y * e0 + h1.y * e1 + h2.y * e2 + h3.y * e3;
        den += (e0 + e1) + (e2 + e3);
    }
    for (; j < cnt; j++) {
        int s0 = eb[j];
        float t0 = g_asrc[s0];
        float2 h0 = *(const float2*)&g_h[2 * s0];
        float e0 = eexp(lrelu_b(t0 + adn), nmm);
        a0 += h0.x * e0; a1 += h0.y * e0; den += e0;
    }
    float inv = __frcp_rn(den);
    float z0 = a0 * inv + b3[0];
    float z1 = a1 * inv + b3[1];
    float mx = fmaxf(z0, z1);
    float lse = mx + logf(expf(z0 - mx) + expf(z1 - mx));
    out[2 * n] = z0 - lse;
    out[2 * n + 1] = z1 - lse;
}

// ---------------- host ------------------------------------------------------
extern "C" void kernel_launch(void* const* d_in, const int* in_sizes, int n_in,
                              void* d_out, int out_size) {
    const float* x   = (const float*)d_in[0];
    const int*   ei  = (const int*)d_in[1];
    const float* W1  = (const float*)d_in[2];
    const float* as1 = (const float*)d_in[3];
    const float* ad1 = (const float*)d_in[4];
    const float* b1  = (const float*)d_in[5];
    const float* W2  = (const float*)d_in[6];
    const float* as2 = (const float*)d_in[7];
    const float* ad2 = (const float*)d_in[8];
    const float* b2  = (const float*)d_in[9];
    const float* W3  = (const float*)d_in[10];
    const float* as3 = (const float*)d_in[11];
    const float* ad3 = (const float*)d_in[12];
    const float* b3  = (const float*)d_in[13];
    float* out = (float*)d_out;

    float *p_agg, *p_agg2;
    cudaGetSymbolAddress((void**)&p_agg, g_agg);
    cudaGetSymbolAddress((void**)&p_agg2, g_agg2);

    const int TB = 256;
    const size_t SMEM1 = (size_t)(64 * XS_STRIDE + 128 * WS_STRIDE) * 4;
    const size_t SMEM2 = (size_t)(128 * XS2_STRIDE + 128 * WS2_STRIDE) * 4;

    static cudaStream_t s1 = nullptr;
    static cudaEvent_t ev0 = nullptr, ev1 = nullptr;
    if (!s1) {
        cudaFuncSetAttribute(k_gemm1_mma, cudaFuncAttributeMaxDynamicSharedMemorySize,
                             (int)SMEM1);
        cudaFuncSetAttribute(k_gemm2_mma, cudaFuncAttributeMaxDynamicSharedMemorySize,
                             (int)SMEM2);
        cudaStreamCreateWithFlags(&s1, cudaStreamNonBlocking);
        cudaEventCreateWithFlags(&ev0, cudaEventDisableTiming);
        cudaEventCreateWithFlags(&ev1, cudaEventDisableTiming);
    }

    // ---- setup, then fork: scatter (s1) || gemm1 (legacy) ----
    k_setup<<<NB_SETUP, 1024>>>(ei);
    cudaEventRecord(ev0, 0);
    cudaStreamWaitEvent(s1, ev0, 0);
    k_scatter<<<(NE + TB * 8 - 1) / (TB * 8), TB, 0, s1>>>(ei);
    cudaEventRecord(ev1, s1);

    k_gemm1_mma<<<(NN + 63) / 64, TB, SMEM1>>>(x, W1, as1, ad1);

    // join: agg1 needs both gemm1 (legacy) and scatter (s1)
    cudaStreamWaitEvent(0, ev1, 0);

    // ---- layer 1 (H=4, O=32, F=128) ----
    k_agg1<<<(NN + 7) / 8, TB>>>(b1);

    // ---- layer 2 (H=2, O=16, F=32) ----
    k_gemm2_mma<<<(NN + 127) / 128, TB, SMEM2>>>(p_agg, W2, as2, ad2);
    k_agg2<<<(NN * 8 + TB - 1) / TB, TB>>>(b2);

    // ---- layer 3 (H=1, O=2, F=2) ----
    k_gemm3<<<(NN + TB - 1) / TB, TB>>>(p_agg2, W3, as3, ad3);
    k_agg3<<<(NN + TB - 1) / TB, TB>>>(b3, out);
}

// round 15
// speedup vs baseline: 1.4478x; 1.4478x over previous
#include <cuda_runtime.h>
#include <cuda_fp16.h>
#include <math.h>
#include <stdint.h>

#define NN 100000
#define NE 1600000
#define NEG_SLOPE 0.2f
#define NB_SETUP 98   // ceil(NN/1024)
#define CAP 128       // bucket capacity per dst (P(deg>=128) ~ 1e-55)
#define LOG2E 1.44269504f

#define XS_STRIDE 132
#define WS_STRIDE 136
#define XS2_STRIDE 132
#define WS2_STRIDE 36

// ---------------- scratch (device globals; no allocations allowed) ----------
__device__ float  g_h[NN * 2];       // layer-3 h (f32, tiny)
__device__ __half g_h16[NN * 128];   // fp16 messages for layers 1/2
__device__ float  g_agg[NN * 128];   // layer-1 output (ELU'd) -> layer-2 input
__device__ float  g_agg2[NN * 32];   // layer-2 output (ELU'd) -> layer-3 input
__device__ float  g_asrc[NN * 4];
__device__ float  g_adst[NN * 4];
__device__ float  g_gm1[8];          // [0..3]=max asrc per head, [4..7]=max adst
__device__ float  g_gm2[4];          // [s0,s1,d0,d1]
__device__ float  g_gm3[2];          // [s,d]
__device__ int    g_eb[(size_t)NN * CAP];  // bucketed src ids per dst
__device__ int    g_cnt[NN];
__device__ int    g_is64;

// ---------------- helpers ---------------------------------------------------
__device__ __forceinline__ void atomicMaxF(float* a, float v) {
    if (v >= 0.f) atomicMax((int*)a, __float_as_int(v));
    else          atomicMin((unsigned int*)a, __float_as_uint(v));
}
__device__ __forceinline__ float lrelu(float v) { return v > 0.f ? v : NEG_SLOPE * v; }
__device__ __forceinline__ float lrelu_b(float v) {
    return fmaxf(v, 0.f) + NEG_SLOPE * fminf(v, 0.f);
}
__device__ __forceinline__ float eexp(float lr, float nmm) {
    return exp2f(fmaf(lr, LOG2E, nmm));
}
__device__ __forceinline__ uint32_t f2tf32(float f) {
    uint32_t r;
    asm("cvt.rna.tf32.f32 %0, %1;" : "=r"(r) : "f"(f));
    return r;
}
__device__ __forceinline__ void mma_tf32(float4& d,
                                         uint32_t a0, uint32_t a1, uint32_t a2, uint32_t a3,
                                         uint32_t b0, uint32_t b1) {
    asm("mma.sync.aligned.m16n8k8.row.col.f32.tf32.tf32.f32 "
        "{%0,%1,%2,%3}, {%4,%5,%6,%7}, {%8,%9}, {%0,%1,%2,%3};"
        : "+f"(d.x), "+f"(d.y), "+f"(d.z), "+f"(d.w)
        : "r"(a0), "r"(a1), "r"(a2), "r"(a3), "r"(b0), "r"(b1));
}
__device__ __forceinline__ float4 cvt4(uint2 u) {
    float2 a = __half22float2(*(__half2*)&u.x);
    float2 b = __half22float2(*(__half2*)&u.y);
    return make_float4(a.x, a.y, b.x, b.y);
}

// ---------------- stage 0: detect dtype, zero counts, reset maxima ----------
__global__ void k_setup(const int* __restrict__ w) {
    int i = blockIdx.x * blockDim.x + threadIdx.x;
    if (i < NN) g_cnt[i] = 0;
    if (i == 0) {
        int any = 0;
        for (int k = 0; k < 128; k++) any |= w[2 * k + 1];
        g_is64 = (any == 0) ? 1 : 0;
        for (int k = 0; k < 8; k++) g_gm1[k] = -INFINITY;
        for (int k = 0; k < 4; k++) g_gm2[k] = -INFINITY;
        g_gm3[0] = -INFINITY; g_gm3[1] = -INFINITY;
    }
}

// scatter src ids into per-dst buckets (counts + payload in one pass)
__global__ void k_scatter(const int* __restrict__ w) {
    int base = (blockIdx.x * blockDim.x + threadIdx.x) * 8;
    int is64 = g_is64;
#pragma unroll
    for (int k = 0; k < 8; k++) {
        int i = base + k;
        if (i < NE) {
            int s = is64 ? w[2 * i] : w[i];
            int d = is64 ? w[2 * (NE + i)] : w[NE + i];
            int p = atomicAdd(&g_cnt[d], 1);
            if (p < CAP) g_eb[(size_t)d * CAP + p] = s;
        }
    }
}

// ---------------- GEMM 1 via tf32 mma.sync + att dots + fused gmax ----------
__global__ void __launch_bounds__(256) k_gemm1_mma(
        const float* __restrict__ X, const float* __restrict__ W,
        const float* __restrict__ as, const float* __restrict__ ad) {
    extern __shared__ uint32_t sm[];
    uint32_t* xs = sm;                  // [64][XS_STRIDE]
    uint32_t* ws = sm + 64 * XS_STRIDE; // [128][WS_STRIDE]
    __shared__ float sgm[8];
    int t = threadIdx.x;
    if (t < 8) sgm[t] = -INFINITY;
    int row0 = blockIdx.x * 64;

    const float4* Xv = (const float4*)X;
#pragma unroll
    for (int i = 0; i < 8; i++) {
        int idx = t + i * 256;
        int row = idx >> 5, cv = idx & 31;
        float4 xv = (row0 + row < NN) ? Xv[(size_t)(row0 + row) * 32 + cv]
                                      : make_float4(0.f, 0.f, 0.f, 0.f);
        uint32_t* p = &xs[row * XS_STRIDE + cv * 4];
        p[0] = f2tf32(xv.x); p[1] = f2tf32(xv.y);
        p[2] = f2tf32(xv.z); p[3] = f2tf32(xv.w);
    }
    const float4* Wv = (const float4*)W;
#pragma unroll
    for (int i = 0; i < 16; i++) {
        int idx = t + i * 256;
        int k = idx >> 5, nv = idx & 31;
        float4 wv = Wv[idx];
        uint32_t* p = &ws[k * WS_STRIDE + nv * 4];
        p[0] = f2tf32(wv.x); p[1] = f2tf32(wv.y);
        p[2] = f2tf32(wv.z); p[3] = f2tf32(wv.w);
    }
    __syncthreads();

    int w = t >> 5, lane = t & 31;
    int r0w = (w >> 1) * 16;
    int c0 = (w & 1) * 64;
    int g = lane >> 2, tg = lane & 3;

    float4 acc[8];
#pragma unroll
    for (int i = 0; i < 8; i++) acc[i] = make_float4(0.f, 0.f, 0.f, 0.f);

#pragma unroll
    for (int kt = 0; kt < 16; kt++) {
        int k0 = kt * 8;
        uint32_t a0 = xs[(r0w + g) * XS_STRIDE + k0 + tg];
        uint32_t a1 = xs[(r0w + g + 8) * XS_STRIDE + k0 + tg];
        uint32_t a2 = xs[(r0w + g) * XS_STRIDE + k0 + tg + 4];
        uint32_t a3 = xs[(r0w + g + 8) * XS_STRIDE + k0 + tg + 4];
#pragma unroll
        for (int ti = 0; ti < 8; ti++) {
            int n0 = c0 + ti * 8 + g;
            uint32_t b0 = ws[(k0 + tg) * WS_STRIDE + n0];
            uint32_t b1 = ws[(k0 + tg + 4) * WS_STRIDE + n0];
            mma_tf32(acc[ti], a0, a1, a2, a3, b0, b1);
        }
    }

    int grow_l = row0 + r0w + g;
    int grow_h = grow_l + 8;
    int hb = c0 >> 5;   // head base for this warp (0 or 2)
    float psl[2] = {0.f, 0.f}, pdl[2] = {0.f, 0.f};
    float psh[2] = {0.f, 0.f}, pdh[2] = {0.f, 0.f};
#pragma unroll
    for (int ti = 0; ti < 8; ti++) {
        int gc = c0 + ti * 8 + tg * 2;
        float s0 = __ldg(&as[gc]), s1 = __ldg(&as[gc + 1]);
        float d0 = __ldg(&ad[gc]), d1 = __ldg(&ad[gc + 1]);
        int hi = ti >> 2;
        psl[hi] += acc[ti].x * s0 + acc[ti].y * s1;
        pdl[hi] += acc[ti].x * d0 + acc[ti].y * d1;
        psh[hi] += acc[ti].z * s0 + acc[ti].w * s1;
        pdh[hi] += acc[ti].z * d0 + acc[ti].w * d1;
        if (grow_l < NN)
            *(__half2*)&g_h16[(size_t)grow_l * 128 + gc] =
                __float22half2_rn(make_float2(acc[ti].x, acc[ti].y));
        if (grow_h < NN)
            *(__half2*)&g_h16[(size_t)grow_h * 128 + gc] =
                __float22half2_rn(make_float2(acc[ti].z, acc[ti].w));
    }
#pragma unroll
    for (int off = 1; off <= 2; off <<= 1) {
#pragma unroll
        for (int i = 0; i < 2; i++) {
            psl[i] += __shfl_xor_sync(0xffffffffu, psl[i], off);
            pdl[i] += __shfl_xor_sync(0xffffffffu, pdl[i], off);
            psh[i] += __shfl_xor_sync(0xffffffffu, psh[i], off);
            pdh[i] += __shfl_xor_sync(0xffffffffu, pdh[i], off);
        }
    }
    if (tg == 0) {
        if (grow_l < NN) {
            g_asrc[grow_l * 4 + hb]     = psl[0];
            g_asrc[grow_l * 4 + hb + 1] = psl[1];
            g_adst[grow_l * 4 + hb]     = pdl[0];
            g_adst[grow_l * 4 + hb + 1] = pdl[1];
        }
        if (grow_h < NN) {
            g_asrc[grow_h * 4 + hb]     = psh[0];
            g_asrc[grow_h * 4 + hb + 1] = psh[1];
            g_adst[grow_h * 4 + hb]     = pdh[0];
            g_adst[grow_h * 4 + hb + 1] = pdh[1];
        }
    }
    float ms[2], md[2];
#pragma unroll
    for (int i = 0; i < 2; i++) {
        float al = (grow_l < NN) ? psl[i] : -INFINITY;
        float ah = (grow_h < NN) ? psh[i] : -INFINITY;
        ms[i] = fmaxf(al, ah);
        float bl = (grow_l < NN) ? pdl[i] : -INFINITY;
        float bh = (grow_h < NN) ? pdh[i] : -INFINITY;
        md[i] = fmaxf(bl, bh);
    }
#pragma unroll
    for (int off = 4; off <= 16; off <<= 1)
#pragma unroll
        for (int i = 0; i < 2; i++) {
            ms[i] = fmaxf(ms[i], __shfl_xor_sync(0xffffffffu, ms[i], off));
            md[i] = fmaxf(md[i], __shfl_xor_sync(0xffffffffu, md[i], off));
        }
    if (lane == 0) {
#pragma unroll
        for (int i = 0; i < 2; i++) {
            atomicMaxF(&sgm[hb + i], ms[i]);
            atomicMaxF(&sgm[4 + hb + i], md[i]);
        }
    }
    __syncthreads();
    if (t < 8) atomicMaxF(&g_gm1[t], sgm[t]);
}

// ---------------- GEMM 2 via tf32 mma.sync + att dots + fused gmax ----------
__global__ void __launch_bounds__(256) k_gemm2_mma(
        const float* __restrict__ X, const float* __restrict__ W,
        const float* __restrict__ as, const float* __restrict__ ad) {
    extern __shared__ uint32_t sm2[];
    uint32_t* xs = sm2;                     // [128][XS2_STRIDE]
    uint32_t* ws = sm2 + 128 * XS2_STRIDE;  // [128][WS2_STRIDE]
    __shared__ float sgm[4];
    int t = threadIdx.x;
    if (t < 4) sgm[t] = -INFINITY;
    int row0 = blockIdx.x * 128;

    const float4* Xv = (const float4*)X;
#pragma unroll
    for (int i = 0; i < 16; i++) {
        int idx = t + i * 256;
        int row = idx >> 5, cv = idx & 31;
        float4 xv = (row0 + row < NN) ? Xv[(size_t)(row0 + row) * 32 + cv]
                                      : make_float4(0.f, 0.f, 0.f, 0.f);
        uint32_t* p = &xs[row * XS2_STRIDE + cv * 4];
        p[0] = f2tf32(xv.x); p[1] = f2tf32(xv.y);
        p[2] = f2tf32(xv.z); p[3] = f2tf32(xv.w);
    }
    const float4* Wv = (const float4*)W;
#pragma unroll
    for (int i = 0; i < 4; i++) {
        int idx = t + i * 256;
        int k = idx >> 3, nv = idx & 7;
        float4 wv = Wv[idx];
        uint32_t* p = &ws[k * WS2_STRIDE + nv * 4];
        p[0] = f2tf32(wv.x); p[1] = f2tf32(wv.y);
        p[2] = f2tf32(wv.z); p[3] = f2tf32(wv.w);
    }
    __syncthreads();

    int w = t >> 5, lane = t & 31;
    int r0w = w * 16;
    int g = lane >> 2, tg = lane & 3;

    float4 acc[4];
#pragma unroll
    for (int i = 0; i < 4; i++) acc[i] = make_float4(0.f, 0.f, 0.f, 0.f);

#pragma unroll
    for (int kt = 0; kt < 16; kt++) {
        int k0 = kt * 8;
        uint32_t a0 = xs[(r0w + g) * XS2_STRIDE + k0 + tg];
        uint32_t a1 = xs[(r0w + g + 8) * XS2_STRIDE + k0 + tg];
        uint32_t a2 = xs[(r0w + g) * XS2_STRIDE + k0 + tg + 4];
        uint32_t a3 = xs[(r0w + g + 8) * XS2_STRIDE + k0 + tg + 4];
#pragma unroll
        for (int ti = 0; ti < 4; ti++) {
            int n0 = ti * 8 + g;
            uint32_t b0 = ws[(k0 + tg) * WS2_STRIDE + n0];
            uint32_t b1 = ws[(k0 + tg + 4) * WS2_STRIDE + n0];
            mma_tf32(acc[ti], a0, a1, a2, a3, b0, b1);
        }
    }

    int grow_l = row0 + r0w + g;
    int grow_h = grow_l + 8;
    float psl[2] = {0.f, 0.f}, pdl[2] = {0.f, 0.f};
    float psh[2] = {0.f, 0.f}, pdh[2] = {0.f, 0.f};
#pragma unroll
    for (int ti = 0; ti < 4; ti++) {
        int gc = ti * 8 + tg * 2;
        float s0 = __ldg(&as[gc]), s1 = __ldg(&as[gc + 1]);
        float d0 = __ldg(&ad[gc]), d1 = __ldg(&ad[gc + 1]);
        int hi = ti >> 1;
        psl[hi] += acc[ti].x * s0 + acc[ti].y * s1;
        pdl[hi] += acc[ti].x * d0 + acc[ti].y * d1;
        psh[hi] += acc[ti].z * s0 + acc[ti].w * s1;
        pdh[hi] += acc[ti].z * d0 + acc[ti].w * d1;
        if (grow_l < NN)
            *(__half2*)&g_h16[(size_t)grow_l * 32 + gc] =
                __float22half2_rn(make_float2(acc[ti].x, acc[ti].y));
        if (grow_h < NN)
            *(__half2*)&g_h16[(size_t)grow_h * 32 + gc] =
                __float22half2_rn(make_float2(acc[ti].z, acc[ti].w));
    }
#pragma unroll
    for (int off = 1; off <= 2; off <<= 1) {
#pragma unroll
        for (int i = 0; i < 2; i++) {
            psl[i] += __shfl_xor_sync(0xffffffffu, psl[i], off);
            pdl[i] += __shfl_xor_sync(0xffffffffu, pdl[i], off);
            psh[i] += __shfl_xor_sync(0xffffffffu, psh[i], off);
            pdh[i] += __shfl_xor_sync(0xffffffffu, pdh[i], off);
        }
    }
    if (tg == 0) {
        if (grow_l < NN) {
            g_asrc[grow_l * 2]     = psl[0];
            g_asrc[grow_l * 2 + 1] = psl[1];
            g_adst[grow_l * 2]     = pdl[0];
            g_adst[grow_l * 2 + 1] = pdl[1];
        }
        if (grow_h < NN) {
            g_asrc[grow_h * 2]     = psh[0];
            g_asrc[grow_h * 2 + 1] = psh[1];
            g_adst[grow_h * 2]     = pdh[0];
            g_adst[grow_h * 2 + 1] = pdh[1];
        }
    }
    float ms[2], md[2];
#pragma unroll
    for (int i = 0; i < 2; i++) {
        float al = (grow_l < NN) ? psl[i] : -INFINITY;
        float ah = (grow_h < NN) ? psh[i] : -INFINITY;
        ms[i] = fmaxf(al, ah);
        float bl = (grow_l < NN) ? pdl[i] : -INFINITY;
        float bh = (grow_h < NN) ? pdh[i] : -INFINITY;
        md[i] = fmaxf(bl, bh);
    }
#pragma unroll
    for (int off = 4; off <= 16; off <<= 1)
#pragma unroll
        for (int i = 0; i < 2; i++) {
            ms[i] = fmaxf(ms[i], __shfl_xor_sync(0xffffffffu, ms[i], off));
            md[i] = fmaxf(md[i], __shfl_xor_sync(0xffffffffu, md[i], off));
        }
    if (lane == 0) {
#pragma unroll
        for (int i = 0; i < 2; i++) {
            atomicMaxF(&sgm[i], ms[i]);
            atomicMaxF(&sgm[2 + i], md[i]);
        }
    }
    __syncthreads();
    if (t < 4) atomicMaxF(&g_gm2[t], sgm[t]);
}

// ---------------- layer 3 GEMM + att dots + fused gmax ----------------------
__global__ void k_gemm3(const float* __restrict__ X, const float* __restrict__ W,
                        const float* __restrict__ as, const float* __restrict__ ad) {
    __shared__ float sgm[2];
    int t = threadIdx.x;
    if (t < 2) sgm[t] = -INFINITY;
    __syncthreads();
    int n = blockIdx.x * blockDim.x + t;
    float asv = -INFINITY, adv = -INFINITY;
    if (n < NN) {
        float h0 = 0.f, h1 = 0.f;
#pragma unroll
        for (int k = 0; k < 32; k++) {
            float xv = X[n * 32 + k];
            h0 += xv * W[2 * k]; h1 += xv * W[2 * k + 1];
        }
        g_h[2 * n] = h0; g_h[2 * n + 1] = h1;
        asv = h0 * as[0] + h1 * as[1];
        adv = h0 * ad[0] + h1 * ad[1];
        g_asrc[n] = asv; g_adst[n] = adv;
    }
    float ms = asv, md = adv;
#pragma unroll
    for (int off = 16; off >= 1; off >>= 1) {
        ms = fmaxf(ms, __shfl_xor_sync(0xffffffffu, ms, off));
        md = fmaxf(md, __shfl_xor_sync(0xffffffffu, md, off));
    }
    if ((t & 31) == 0) { atomicMaxF(&sgm[0], ms); atomicMaxF(&sgm[1], md); }
    __syncthreads();
    if (t < 2) atomicMaxF(&g_gm3[t], sgm[t]);
}

// ---------------- bucket aggregation ----------------------------------------
// Layer 1: F=128, H=4. One warp per dst node, two-phase (f32 weights).
// Phase 1: lanes stride bucket slots; per-edge 4-head exps computed ONCE,
//          stored transposed (sew[h*CAP+j]); per-head denominators
//          accumulated + warp-reduced here.
// Phase 2: lane owns 4 features; 8 edges per iteration, all loads batched
//          (2x int4 ids + 2x LDS.128 weights + 8x LDG.64 messages in flight).
__global__ void __launch_bounds__(256) k_agg1(const float* __restrict__ b) {
    __shared__ float sew[8][4 * CAP];   // 16 KB: per-warp transposed edge weights
    int wid = threadIdx.x >> 5, lane = threadIdx.x & 31;
    int n = blockIdx.x * 8 + wid;
    if (n >= NN) return;
    float* sew_w = sew[wid];

    float4 gs = *(const float4*)&g_gm1[0];
    float4 gd = *(const float4*)&g_gm1[4];
    float nm0 = -lrelu_b(gs.x + gd.x) * LOG2E;
    float nm1 = -lrelu_b(gs.y + gd.y) * LOG2E;
    float nm2 = -lrelu_b(gs.z + gd.z) * LOG2E;
    float nm3 = -lrelu_b(gs.w + gd.w) * LOG2E;
    float4 ad4 = *(const float4*)&g_adst[n * 4];

    const int* eb = &g_eb[(size_t)n * CAP];
    int cnt = min(g_cnt[n], CAP);

    // phase 1: per-edge weights (once) + per-head denominator partials
    float d0 = 0.f, d1 = 0.f, d2 = 0.f, d3 = 0.f;
    for (int j = lane; j < cnt; j += 32) {
        int s = __ldg(&eb[j]);
        float4 a4 = *(const float4*)&g_asrc[s * 4];
        float e0 = eexp(lrelu_b(a4.x + ad4.x), nm0);
        float e1 = eexp(lrelu_b(a4.y + ad4.y), nm1);
        float e2 = eexp(lrelu_b(a4.z + ad4.z), nm2);
        float e3 = eexp(lrelu_b(a4.w + ad4.w), nm3);
        sew_w[j]           = e0;
        sew_w[CAP + j]     = e1;
        sew_w[2 * CAP + j] = e2;
        sew_w[3 * CAP + j] = e3;
        d0 += e0; d1 += e1; d2 += e2; d3 += e3;
    }
#pragma unroll
    for (int off = 16; off >= 1; off >>= 1) {
        d0 += __shfl_xor_sync(0xffffffffu, d0, off);
        d1 += __shfl_xor_sync(0xffffffffu, d1, off);
        d2 += __shfl_xor_sync(0xffffffffu, d2, off);
        d3 += __shfl_xor_sync(0xffffffffu, d3, off);
    }
    __syncwarp();

    // phase 2: feature accumulation, 8 edges/iter
    int h = lane >> 3, c0 = lane * 4;
    float ta = (h & 2) ? nm2 : nm0;
    float tb = (h & 2) ? nm3 : nm1;
    float nmm = (h & 1) ? tb : ta;
    float da = (h & 2) ? d2 : d0;
    float db = (h & 2) ? d3 : d1;
    float dh = (h & 1) ? db : da;
    float adn = g_adst[n * 4 + h];
    float es = eexp(lrelu_b(g_asrc[n * 4 + h] + adn), nmm);
    float4 hv = cvt4(*(const uint2*)&g_h16[(size_t)n * 128 + c0]);
    float ax = hv.x * es, ay = hv.y * es, az = hv.z * es, aw = hv.w * es;
    float den = dh + es;
    const float* ep = sew_w + h * CAP;
    int j = 0;
    for (; j + 8 <= cnt; j += 8) {
        int4 sA = *(const int4*)(eb + j);
        int4 sB = *(const int4*)(eb + j + 4);
        float4 eA = *(const float4*)&ep[j];
        float4 eB = *(const float4*)&ep[j + 4];
        uint2 u0 = *(const uint2*)&g_h16[(size_t)sA.x * 128 + c0];
        uint2 u1 = *(const uint2*)&g_h16[(size_t)sA.y * 128 + c0];
        uint2 u2 = *(const uint2*)&g_h16[(size_t)sA.z * 128 + c0];
        uint2 u3 = *(const uint2*)&g_h16[(size_t)sA.w * 128 + c0];
        uint2 u4 = *(const uint2*)&g_h16[(size_t)sB.x * 128 + c0];
        uint2 u5 = *(const uint2*)&g_h16[(size_t)sB.y * 128 + c0];
        uint2 u6 = *(const uint2*)&g_h16[(size_t)sB.z * 128 + c0];
        uint2 u7 = *(const uint2*)&g_h16[(size_t)sB.w * 128 + c0];
        float4 h0 = cvt4(u0), h1 = cvt4(u1), h2 = cvt4(u2), h3 = cvt4(u3);
        ax += h0.x * eA.x + h1.x * eA.y + h2.x * eA.z + h3.x * eA.w;
        ay += h0.y * eA.x + h1.y * eA.y + h2.y * eA.z + h3.y * eA.w;
        az += h0.z * eA.x + h1.z * eA.y + h2.z * eA.z + h3.z * eA.w;
        aw += h0.w * eA.x + h1.w * eA.y + h2.w * eA.z + h3.w * eA.w;
        float4 h4 = cvt4(u4), h5 = cvt4(u5), h6 = cvt4(u6), h7 = cvt4(u7);
        ax += h4.x * eB.x + h5.x * eB.y + h6.x * eB.z + h7.x * eB.w;
        ay += h4.y * eB.x + h5.y * eB.y + h6.y * eB.z + h7.y * eB.w;
        az += h4.z * eB.x + h5.z * eB.y + h6.z * eB.z + h7.z * eB.w;
        aw += h4.w * eB.x + h5.w * eB.y + h6.w * eB.z + h7.w * eB.w;
    }
    for (; j < cnt; j++) {
        int s0 = eb[j];
        float e0 = ep[j];
        float4 h0 = cvt4(*(const uint2*)&g_h16[(size_t)s0 * 128 + c0]);
        ax += h0.x * e0; ay += h0.y * e0; az += h0.z * e0; aw += h0.w * e0;
    }
    float inv = __frcp_rn(den);
    float4 bv = *(const float4*)&b[c0];
    float vx = ax * inv + bv.x, vy = ay * inv + bv.y;
    float vz = az * inv + bv.z, vw = aw * inv + bv.w;
    vx = vx > 0.f ? vx : expm1f(vx);
    vy = vy > 0.f ? vy : expm1f(vy);
    vz = vz > 0.f ? vz : expm1f(vz);
    vw = vw > 0.f ? vw : expm1f(vw);
    *(float4*)&g_agg[(size_t)n * 128 + c0] = make_float4(vx, vy, vz, vw);
}

// Layer 2: F=32, H=2. 8 lanes per dst node (round-10 proven form).
__global__ void __launch_bounds__(256) k_agg2(const float* __restrict__ b) {
    int gi = blockIdx.x * blockDim.x + threadIdx.x;
    int n = gi >> 3, jl = gi & 7;
    if (n >= NN) return;
    int h = jl >> 2, c0 = jl * 4;
    float m = lrelu(g_gm2[h] + g_gm2[2 + h]);
    float nmm = -m * LOG2E;
    float adn = g_adst[n * 2 + h];
    float es = eexp(lrelu_b(g_asrc[n * 2 + h] + adn), nmm);
    float4 hv = cvt4(*(const uint2*)&g_h16[n * 32 + c0]);
    float ax = hv.x * es, ay = hv.y * es, az = hv.z * es, aw = hv.w * es;
    float den = es;
    const int* eb = &g_eb[(size_t)n * CAP];
    int cnt = min(g_cnt[n], CAP);
    int j = 0;
    for (; j + 4 <= cnt; j += 4) {
        int4 s4 = *(const int4*)(eb + j);
        float a0 = g_asrc[s4.x * 2 + h];
        float a1 = g_asrc[s4.y * 2 + h];
        float a2 = g_asrc[s4.z * 2 + h];
        float a3 = g_asrc[s4.w * 2 + h];
        uint2 u0 = *(const uint2*)&g_h16[s4.x * 32 + c0];
        uint2 u1 = *(const uint2*)&g_h16[s4.y * 32 + c0];
        uint2 u2 = *(const uint2*)&g_h16[s4.z * 32 + c0];
        uint2 u3 = *(const uint2*)&g_h16[s4.w * 32 + c0];
        float e0 = eexp(lrelu_b(a0 + adn), nmm);
        float e1 = eexp(lrelu_b(a1 + adn), nmm);
        float e2 = eexp(lrelu_b(a2 + adn), nmm);
        float e3 = eexp(lrelu_b(a3 + adn), nmm);
        float4 h0 = cvt4(u0), h1 = cvt4(u1), h2 = cvt4(u2), h3 = cvt4(u3);
        ax += h0.x * e0 + h1.x * e1 + h2.x * e2 + h3.x * e3;
        ay += h0.y * e0 + h1.y * e1 + h2.y * e2 + h3.y * e3;
        az += h0.z * e0 + h1.z * e1 + h2.z * e2 + h3.z * e3;
        aw += h0.w * e0 + h1.w * e1 + h2.w * e2 + h3.w * e3;
        den += (e0 + e1) + (e2 + e3);
    }
    for (; j < cnt; j++) {
        int s0 = eb[j];
        float a0 = g_asrc[s0 * 2 + h];
        uint2 u0 = *(const uint2*)&g_h16[s0 * 32 + c0];
        float e0 = eexp(lrelu_b(a0 + adn), nmm);
        float4 h0 = cvt4(u0);
        ax += h0.x * e0; ay += h0.y * e0; az += h0.z * e0; aw += h0.w * e0;
        den += e0;
    }
    float inv = __frcp_rn(den);
    float4 bv = *(const float4*)&b[c0];
    float vx = ax * inv + bv.x, vy = ay * inv + bv.y;
    float vz = az * inv + bv.z, vw = aw * inv + bv.w;
    vx = vx > 0.f ? vx : expm1f(vx);
    vy = vy > 0.f ? vy : expm1f(vy);
    vz = vz > 0.f ? vz : expm1f(vz);
    vw = vw > 0.f ? vw : expm1f(vw);
    *(float4*)&g_agg2[n * 32 + c0] = make_float4(vx, vy, vz, vw);
}

// Layer 3: F=2, H=1. One thread per dst node + fused log-softmax.
__global__ void k_agg3(const float* __restrict__ b3, float* __restrict__ out) {
    int n = blockIdx.x * blockDim.x + threadIdx.x;
    if (n >= NN) return;
    float m = lrelu(g_gm3[0] + g_gm3[1]);
    float nmm = -m * LOG2E;
    float adn = g_adst[n];
    float es = eexp(lrelu_b(g_asrc[n] + adn), nmm);
    float2 hv = *(const float2*)&g_h[2 * n];
    float a0 = hv.x * es, a1 = hv.y * es, den = es;
    const int* eb = &g_eb[(size_t)n * CAP];
    int cnt = min(g_cnt[n], CAP);
    int j = 0;
    for (; j + 4 <= cnt; j += 4) {
        int4 s4 = *(const int4*)(eb + j);
        float t0 = g_asrc[s4.x], t1 = g_asrc[s4.y];
        float t2 = g_asrc[s4.z], t3 = g_asrc[s4.w];
        float2 h0 = *(const float2*)&g_h[2 * s4.x];
        float2 h1 = *(const float2*)&g_h[2 * s4.y];
        float2 h2 = *(const float2*)&g_h[2 * s4.z];
        float2 h3 = *(const float2*)&g_h[2 * s4.w];
        float e0 = eexp(lrelu_b(t0 + adn), nmm);
        float e1 = eexp(lrelu_b(t1 + adn), nmm);
        float e2 = eexp(lrelu_b(t2 + adn), nmm);
        float e3 = eexp(lrelu_b(t3 + adn), nmm);
        a0 += h0.x * e0 + h1.x * e1 + h2.x * e2 + h3.x * e3;
        a1 += h0.y * e0 + h1.y * e1 + h2.y * e2 + h3.y * e3;
        den += (e0 + e1) + (e2 + e3);
    }
    for (; j < cnt; j++) {
        int s0 = eb[j];
        float t0 = g_asrc[s0];
        float2 h0 = *(const float2*)&g_h[2 * s0];
        float e0 = eexp(lrelu_b(t0 + adn), nmm);
        a0 += h0.x * e0; a1 += h0.y * e0; den += e0;
    }
    float inv = __frcp_rn(den);
    float z0 = a0 * inv + b3[0];
    float z1 = a1 * inv + b3[1];
    float mx = fmaxf(z0, z1);
    float lse = mx + logf(expf(z0 - mx) + expf(z1 - mx));
    out[2 * n] = z0 - lse;
    out[2 * n + 1] = z1 - lse;
}

// ---------------- host ------------------------------------------------------
extern "C" void kernel_launch(void* const* d_in, const int* in_sizes, int n_in,
                              void* d_out, int out_size) {
    const float* x   = (const float*)d_in[0];
    const int*   ei  = (const int*)d_in[1];
    const float* W1  = (const float*)d_in[2];
    const float* as1 = (const float*)d_in[3];
    const float* ad1 = (const float*)d_in[4];
    const float* b1  = (const float*)d_in[5];
    const float* W2  = (const float*)d_in[6];
    const float* as2 = (const float*)d_in[7];
    const float* ad2 = (const float*)d_in[8];
    const float* b2  = (const float*)d_in[9];
    const float* W3  = (const float*)d_in[10];
    const float* as3 = (const float*)d_in[11];
    const float* ad3 = (const float*)d_in[12];
    const float* b3  = (const float*)d_in[13];
    float* out = (float*)d_out;

    float *p_agg, *p_agg2;
    cudaGetSymbolAddress((void**)&p_agg, g_agg);
    cudaGetSymbolAddress((void**)&p_agg2, g_agg2);

    const int TB = 256;
    const size_t SMEM1 = (size_t)(64 * XS_STRIDE + 128 * WS_STRIDE) * 4;
    const size_t SMEM2 = (size_t)(128 * XS2_STRIDE + 128 * WS2_STRIDE) * 4;

    static cudaStream_t s1 = nullptr;
    static cudaEvent_t ev0 = nullptr, ev1 = nullptr;
    if (!s1) {
        cudaFuncSetAttribute(k_gemm1_mma, cudaFuncAttributeMaxDynamicSharedMemorySize,
                             (int)SMEM1);
        cudaFuncSetAttribute(k_gemm2_mma, cudaFuncAttributeMaxDynamicSharedMemorySize,
                             (int)SMEM2);
        cudaStreamCreateWithFlags(&s1, cudaStreamNonBlocking);
        cudaEventCreateWithFlags(&ev0, cudaEventDisableTiming);
        cudaEventCreateWithFlags(&ev1, cudaEventDisableTiming);
    }

    // ---- setup, then fork: scatter (s1) || gemm1 (legacy) ----
    k_setup<<<NB_SETUP, 1024>>>(ei);
    cudaEventRecord(ev0, 0);
    cudaStreamWaitEvent(s1, ev0, 0);
    k_scatter<<<(NE + TB * 8 - 1) / (TB * 8), TB, 0, s1>>>(ei);
    cudaEventRecord(ev1, s1);

    k_gemm1_mma<<<(NN + 63) / 64, TB, SMEM1>>>(x, W1, as1, ad1);

    // join: agg1 needs both gemm1 (legacy) and scatter (s1)
    cudaStreamWaitEvent(0, ev1, 0);

    // ---- layer 1 (H=4, O=32, F=128) ----
    k_agg1<<<(NN + 7) / 8, TB>>>(b1);

    // ---- layer 2 (H=2, O=16, F=32) ----
    k_gemm2_mma<<<(NN + 127) / 128, TB, SMEM2>>>(p_agg, W2, as2, ad2);
    k_agg2<<<(NN * 8 + TB - 1) / TB, TB>>>(b2);

    // ---- layer 3 (H=1, O=2, F=2) ----
    k_gemm3<<<(NN + TB - 1) / TB, TB>>>(p_agg2, W3, as3, ad3);
    k_agg3<<<(NN + TB - 1) / TB, TB>>>(b3, out);
}

// round 17
// speedup vs baseline: 1.5037x; 1.0386x over previous
#include <cuda_runtime.h>
#include <cuda_fp16.h>
#include <math.h>
#include <stdint.h>

#define NN 100000
#define NE 1600000
#define NEG_SLOPE 0.2f
#define NB_SETUP 98   // ceil(NN/1024)
#define CAP 128       // bucket capacity per dst (P(deg>=128) ~ 1e-55)
#define LOG2E 1.44269504f

#define XS_STRIDE 132
#define WS_STRIDE 136
#define XS2_STRIDE 132
#define WS2_STRIDE 36

// ---------------- scratch (device globals; no allocations allowed) ----------
__device__ float  g_h[NN * 2];       // layer-3 h (f32, tiny)
__device__ __half g_h16[NN * 128];   // fp16 messages for layers 1/2
__device__ __half g_agg16[NN * 128]; // layer-1 output (ELU'd, fp16) -> layer-2 input
__device__ float  g_agg2[NN * 32];   // layer-2 output (ELU'd) -> layer-3 input
__device__ float  g_asrc[NN * 4];
__device__ float  g_adst[NN * 4];
__device__ float  g_gm1[8];          // [0..3]=max asrc per head, [4..7]=max adst
__device__ float  g_gm2[4];          // [s0,s1,d0,d1]
__device__ float  g_gm3[2];          // [s,d]
__device__ int    g_eb[(size_t)NN * CAP];  // bucketed src ids per dst
__device__ int    g_cnt[NN];
__device__ int    g_is64;

// ---------------- helpers ---------------------------------------------------
__device__ __forceinline__ void atomicMaxF(float* a, float v) {
    if (v >= 0.f) atomicMax((int*)a, __float_as_int(v));
    else          atomicMin((unsigned int*)a, __float_as_uint(v));
}
__device__ __forceinline__ float lrelu(float v) { return v > 0.f ? v : NEG_SLOPE * v; }
__device__ __forceinline__ float lrelu_b(float v) {
    return fmaxf(v, 0.f) + NEG_SLOPE * fminf(v, 0.f);
}
__device__ __forceinline__ float eexp(float lr, float nmm) {
    return exp2f(fmaf(lr, LOG2E, nmm));
}
// fast ELU: exp via MUFU instead of expm1f's polynomial (abs err ~1e-7 near 0)
__device__ __forceinline__ float elu_f(float v) {
    return v > 0.f ? v : exp2f(v * LOG2E) - 1.f;
}
__device__ __forceinline__ uint32_t f2tf32(float f) {
    uint32_t r;
    asm("cvt.rna.tf32.f32 %0, %1;" : "=r"(r) : "f"(f));
    return r;
}
__device__ __forceinline__ void mma_tf32(float4& d,
                                         uint32_t a0, uint32_t a1, uint32_t a2, uint32_t a3,
                                         uint32_t b0, uint32_t b1) {
    asm("mma.sync.aligned.m16n8k8.row.col.f32.tf32.tf32.f32 "
        "{%0,%1,%2,%3}, {%4,%5,%6,%7}, {%8,%9}, {%0,%1,%2,%3};"
        : "+f"(d.x), "+f"(d.y), "+f"(d.z), "+f"(d.w)
        : "r"(a0), "r"(a1), "r"(a2), "r"(a3), "r"(b0), "r"(b1));
}
__device__ __forceinline__ float4 cvt4(uint2 u) {
    float2 a = __half22float2(*(__half2*)&u.x);
    float2 b = __half22float2(*(__half2*)&u.y);
    return make_float4(a.x, a.y, b.x, b.y);
}

// ---------------- stage 0: detect dtype, zero counts, reset maxima ----------
__global__ void k_setup(const int* __restrict__ w) {
    int i = blockIdx.x * blockDim.x + threadIdx.x;
    if (i < NN) g_cnt[i] = 0;
    if (i == 0) {
        int any = 0;
        for (int k = 0; k < 128; k++) any |= w[2 * k + 1];
        g_is64 = (any == 0) ? 1 : 0;
        for (int k = 0; k < 8; k++) g_gm1[k] = -INFINITY;
        for (int k = 0; k < 4; k++) g_gm2[k] = -INFINITY;
        g_gm3[0] = -INFINITY; g_gm3[1] = -INFINITY;
    }
}

// scatter src ids into per-dst buckets (counts + payload in one pass)
__global__ void k_scatter(const int* __restrict__ w) {
    int base = (blockIdx.x * blockDim.x + threadIdx.x) * 8;
    int is64 = g_is64;
#pragma unroll
    for (int k = 0; k < 8; k++) {
        int i = base + k;
        if (i < NE) {
            int s = is64 ? w[2 * i] : w[i];
            int d = is64 ? w[2 * (NE + i)] : w[NE + i];
            int p = atomicAdd(&g_cnt[d], 1);
            if (p < CAP) g_eb[(size_t)d * CAP + p] = s;
        }
    }
}

// ---------------- GEMM 1 via tf32 mma.sync + att dots + fused gmax ----------
__global__ void __launch_bounds__(256) k_gemm1_mma(
        const float* __restrict__ X, const float* __restrict__ W,
        const float* __restrict__ as, const float* __restrict__ ad) {
    extern __shared__ uint32_t sm[];
    uint32_t* xs = sm;                  // [64][XS_STRIDE]
    uint32_t* ws = sm + 64 * XS_STRIDE; // [128][WS_STRIDE]
    __shared__ float sgm[8];
    int t = threadIdx.x;
    if (t < 8) sgm[t] = -INFINITY;
    int row0 = blockIdx.x * 64;

    const float4* Xv = (const float4*)X;
#pragma unroll
    for (int i = 0; i < 8; i++) {
        int idx = t + i * 256;
        int row = idx >> 5, cv = idx & 31;
        float4 xv = (row0 + row < NN) ? Xv[(size_t)(row0 + row) * 32 + cv]
                                      : make_float4(0.f, 0.f, 0.f, 0.f);
        uint32_t* p = &xs[row * XS_STRIDE + cv * 4];
        p[0] = f2tf32(xv.x); p[1] = f2tf32(xv.y);
        p[2] = f2tf32(xv.z); p[3] = f2tf32(xv.w);
    }
    const float4* Wv = (const float4*)W;
#pragma unroll
    for (int i = 0; i < 16; i++) {
        int idx = t + i * 256;
        int k = idx >> 5, nv = idx & 31;
        float4 wv = Wv[idx];
        uint32_t* p = &ws[k * WS_STRIDE + nv * 4];
        p[0] = f2tf32(wv.x); p[1] = f2tf32(wv.y);
        p[2] = f2tf32(wv.z); p[3] = f2tf32(wv.w);
    }
    __syncthreads();

    int w = t >> 5, lane = t & 31;
    int r0w = (w >> 1) * 16;
    int c0 = (w & 1) * 64;
    int g = lane >> 2, tg = lane & 3;

    float4 acc[8];
#pragma unroll
    for (int i = 0; i < 8; i++) acc[i] = make_float4(0.f, 0.f, 0.f, 0.f);

#pragma unroll
    for (int kt = 0; kt < 16; kt++) {
        int k0 = kt * 8;
        uint32_t a0 = xs[(r0w + g) * XS_STRIDE + k0 + tg];
        uint32_t a1 = xs[(r0w + g + 8) * XS_STRIDE + k0 + tg];
        uint32_t a2 = xs[(r0w + g) * XS_STRIDE + k0 + tg + 4];
        uint32_t a3 = xs[(r0w + g + 8) * XS_STRIDE + k0 + tg + 4];
#pragma unroll
        for (int ti = 0; ti < 8; ti++) {
            int n0 = c0 + ti * 8 + g;
            uint32_t b0 = ws[(k0 + tg) * WS_STRIDE + n0];
            uint32_t b1 = ws[(k0 + tg + 4) * WS_STRIDE + n0];
            mma_tf32(acc[ti], a0, a1, a2, a3, b0, b1);
        }
    }

    int grow_l = row0 + r0w + g;
    int grow_h = grow_l + 8;
    int hb = c0 >> 5;   // head base for this warp (0 or 2)
    float psl[2] = {0.f, 0.f}, pdl[2] = {0.f, 0.f};
    float psh[2] = {0.f, 0.f}, pdh[2] = {0.f, 0.f};
#pragma unroll
    for (int ti = 0; ti < 8; ti++) {
        int gc = c0 + ti * 8 + tg * 2;
        float s0 = __ldg(&as[gc]), s1 = __ldg(&as[gc + 1]);
        float d0 = __ldg(&ad[gc]), d1 = __ldg(&ad[gc + 1]);
        int hi = ti >> 2;
        psl[hi] += acc[ti].x * s0 + acc[ti].y * s1;
        pdl[hi] += acc[ti].x * d0 + acc[ti].y * d1;
        psh[hi] += acc[ti].z * s0 + acc[ti].w * s1;
        pdh[hi] += acc[ti].z * d0 + acc[ti].w * d1;
        if (grow_l < NN)
            *(__half2*)&g_h16[(size_t)grow_l * 128 + gc] =
                __float22half2_rn(make_float2(acc[ti].x, acc[ti].y));
        if (grow_h < NN)
            *(__half2*)&g_h16[(size_t)grow_h * 128 + gc] =
                __float22half2_rn(make_float2(acc[ti].z, acc[ti].w));
    }
#pragma unroll
    for (int off = 1; off <= 2; off <<= 1) {
#pragma unroll
        for (int i = 0; i < 2; i++) {
            psl[i] += __shfl_xor_sync(0xffffffffu, psl[i], off);
            pdl[i] += __shfl_xor_sync(0xffffffffu, pdl[i], off);
            psh[i] += __shfl_xor_sync(0xffffffffu, psh[i], off);
            pdh[i] += __shfl_xor_sync(0xffffffffu, pdh[i], off);
        }
    }
    if (tg == 0) {
        if (grow_l < NN) {
            g_asrc[grow_l * 4 + hb]     = psl[0];
            g_asrc[grow_l * 4 + hb + 1] = psl[1];
            g_adst[grow_l * 4 + hb]     = pdl[0];
            g_adst[grow_l * 4 + hb + 1] = pdl[1];
        }
        if (grow_h < NN) {
            g_asrc[grow_h * 4 + hb]     = psh[0];
            g_asrc[grow_h * 4 + hb + 1] = psh[1];
            g_adst[grow_h * 4 + hb]     = pdh[0];
            g_adst[grow_h * 4 + hb + 1] = pdh[1];
        }
    }
    float ms[2], md[2];
#pragma unroll
    for (int i = 0; i < 2; i++) {
        float al = (grow_l < NN) ? psl[i] : -INFINITY;
        float ah = (grow_h < NN) ? psh[i] : -INFINITY;
        ms[i] = fmaxf(al, ah);
        float bl = (grow_l < NN) ? pdl[i] : -INFINITY;
        float bh = (grow_h < NN) ? pdh[i] : -INFINITY;
        md[i] = fmaxf(bl, bh);
    }
#pragma unroll
    for (int off = 4; off <= 16; off <<= 1)
#pragma unroll
        for (int i = 0; i < 2; i++) {
            ms[i] = fmaxf(ms[i], __shfl_xor_sync(0xffffffffu, ms[i], off));
            md[i] = fmaxf(md[i], __shfl_xor_sync(0xffffffffu, md[i], off));
        }
    if (lane == 0) {
#pragma unroll
        for (int i = 0; i < 2; i++) {
            atomicMaxF(&sgm[hb + i], ms[i]);
            atomicMaxF(&sgm[4 + hb + i], md[i]);
        }
    }
    __syncthreads();
    if (t < 8) atomicMaxF(&g_gm1[t], sgm[t]);
}

// ---------------- GEMM 2 via tf32 mma.sync + att dots + fused gmax ----------
// X input is fp16 (layer-1 output). [NN,128] @ [128,32].
__global__ void __launch_bounds__(256) k_gemm2_mma(
        const __half* __restrict__ X, const float* __restrict__ W,
        const float* __restrict__ as, const float* __restrict__ ad) {
    extern __shared__ uint32_t sm2[];
    uint32_t* xs = sm2;                     // [128][XS2_STRIDE]
    uint32_t* ws = sm2 + 128 * XS2_STRIDE;  // [128][WS2_STRIDE]
    __shared__ float sgm[4];
    int t = threadIdx.x;
    if (t < 4) sgm[t] = -INFINITY;
    int row0 = blockIdx.x * 128;

    const uint2* Xv = (const uint2*)X;      // 4 halves per uint2, 32 per row
#pragma unroll
    for (int i = 0; i < 16; i++) {
        int idx = t + i * 256;              // 4096 uint2
        int row = idx >> 5, cv = idx & 31;
        uint2 xu = (row0 + row < NN) ? Xv[(size_t)(row0 + row) * 32 + cv]
                                     : make_uint2(0u, 0u);
        float4 xv = cvt4(xu);
        uint32_t* p = &xs[row * XS2_STRIDE + cv * 4];
        p[0] = f2tf32(xv.x); p[1] = f2tf32(xv.y);
        p[2] = f2tf32(xv.z); p[3] = f2tf32(xv.w);
    }
    const float4* Wv = (const float4*)W;
#pragma unroll
    for (int i = 0; i < 4; i++) {
        int idx = t + i * 256;
        int k = idx >> 3, nv = idx & 7;
        float4 wv = Wv[idx];
        uint32_t* p = &ws[k * WS2_STRIDE + nv * 4];
        p[0] = f2tf32(wv.x); p[1] = f2tf32(wv.y);
        p[2] = f2tf32(wv.z); p[3] = f2tf32(wv.w);
    }
    __syncthreads();

    int w = t >> 5, lane = t & 31;
    int r0w = w * 16;
    int g = lane >> 2, tg = lane & 3;

    float4 acc[4];
#pragma unroll
    for (int i = 0; i < 4; i++) acc[i] = make_float4(0.f, 0.f, 0.f, 0.f);

#pragma unroll
    for (int kt = 0; kt < 16; kt++) {
        int k0 = kt * 8;
        uint32_t a0 = xs[(r0w + g) * XS2_STRIDE + k0 + tg];
        uint32_t a1 = xs[(r0w + g + 8) * XS2_STRIDE + k0 + tg];
        uint32_t a2 = xs[(r0w + g) * XS2_STRIDE + k0 + tg + 4];
        uint32_t a3 = xs[(r0w + g + 8) * XS2_STRIDE + k0 + tg + 4];
#pragma unroll
        for (int ti = 0; ti < 4; ti++) {
            int n0 = ti * 8 + g;
            uint32_t b0 = ws[(k0 + tg) * WS2_STRIDE + n0];
            uint32_t b1 = ws[(k0 + tg + 4) * WS2_STRIDE + n0];
            mma_tf32(acc[ti], a0, a1, a2, a3, b0, b1);
        }
    }

    int grow_l = row0 + r0w + g;
    int grow_h = grow_l + 8;
    float psl[2] = {0.f, 0.f}, pdl[2] = {0.f, 0.f};
    float psh[2] = {0.f, 0.f}, pdh[2] = {0.f, 0.f};
#pragma unroll
    for (int ti = 0; ti < 4; ti++) {
        int gc = ti * 8 + tg * 2;
        float s0 = __ldg(&as[gc]), s1 = __ldg(&as[gc + 1]);
        float d0 = __ldg(&ad[gc]), d1 = __ldg(&ad[gc + 1]);
        int hi = ti >> 1;
        psl[hi] += acc[ti].x * s0 + acc[ti].y * s1;
        pdl[hi] += acc[ti].x * d0 + acc[ti].y * d1;
        psh[hi] += acc[ti].z * s0 + acc[ti].w * s1;
        pdh[hi] += acc[ti].z * d0 + acc[ti].w * d1;
        if (grow_l < NN)
            *(__half2*)&g_h16[(size_t)grow_l * 32 + gc] =
                __float22half2_rn(make_float2(acc[ti].x, acc[ti].y));
        if (grow_h < NN)
            *(__half2*)&g_h16[(size_t)grow_h * 32 + gc] =
                __float22half2_rn(make_float2(acc[ti].z, acc[ti].w));
    }
#pragma unroll
    for (int off = 1; off <= 2; off <<= 1) {
#pragma unroll
        for (int i = 0; i < 2; i++) {
            psl[i] += __shfl_xor_sync(0xffffffffu, psl[i], off);
            pdl[i] += __shfl_xor_sync(0xffffffffu, pdl[i], off);
            psh[i] += __shfl_xor_sync(0xffffffffu, psh[i], off);
            pdh[i] += __shfl_xor_sync(0xffffffffu, pdh[i], off);
        }
    }
    if (tg == 0) {
        if (grow_l < NN) {
            g_asrc[grow_l * 2]     = psl[0];
            g_asrc[grow_l * 2 + 1] = psl[1];
            g_adst[grow_l * 2]     = pdl[0];
            g_adst[grow_l * 2 + 1] = pdl[1];
        }
        if (grow_h < NN) {
            g_asrc[grow_h * 2]     = psh[0];
            g_asrc[grow_h * 2 + 1] = psh[1];
            g_adst[grow_h * 2]     = pdh[0];
            g_adst[grow_h * 2 + 1] = pdh[1];
        }
    }
    float ms[2], md[2];
#pragma unroll
    for (int i = 0; i < 2; i++) {
        float al = (grow_l < NN) ? psl[i] : -INFINITY;
        float ah = (grow_h < NN) ? psh[i] : -INFINITY;
        ms[i] = fmaxf(al, ah);
        float bl = (grow_l < NN) ? pdl[i] : -INFINITY;
        float bh = (grow_h < NN) ? pdh[i] : -INFINITY;
        md[i] = fmaxf(bl, bh);
    }
#pragma unroll
    for (int off = 4; off <= 16; off <<= 1)
#pragma unroll
        for (int i = 0; i < 2; i++) {
            ms[i] = fmaxf(ms[i], __shfl_xor_sync(0xffffffffu, ms[i], off));
            md[i] = fmaxf(md[i], __shfl_xor_sync(0xffffffffu, md[i], off));
        }
    if (lane == 0) {
#pragma unroll
        for (int i = 0; i < 2; i++) {
            atomicMaxF(&sgm[i], ms[i]);
            atomicMaxF(&sgm[2 + i], md[i]);
        }
    }
    __syncthreads();
    if (t < 4) atomicMaxF(&g_gm2[t], sgm[t]);
}

// ---------------- layer 3 GEMM + att dots + fused gmax ----------------------
__global__ void k_gemm3(const float* __restrict__ X, const float* __restrict__ W,
                        const float* __restrict__ as, const float* __restrict__ ad) {
    __shared__ float sgm[2];
    int t = threadIdx.x;
    if (t < 2) sgm[t] = -INFINITY;
    __syncthreads();
    int n = blockIdx.x * blockDim.x + t;
    float asv = -INFINITY, adv = -INFINITY;
    if (n < NN) {
        float h0 = 0.f, h1 = 0.f;
#pragma unroll
        for (int k = 0; k < 32; k++) {
            float xv = X[n * 32 + k];
            h0 += xv * W[2 * k]; h1 += xv * W[2 * k + 1];
        }
        g_h[2 * n] = h0; g_h[2 * n + 1] = h1;
        asv = h0 * as[0] + h1 * as[1];
        adv = h0 * ad[0] + h1 * ad[1];
        g_asrc[n] = asv; g_adst[n] = adv;
    }
    float ms = asv, md = adv;
#pragma unroll
    for (int off = 16; off >= 1; off >>= 1) {
        ms = fmaxf(ms, __shfl_xor_sync(0xffffffffu, ms, off));
        md = fmaxf(md, __shfl_xor_sync(0xffffffffu, md, off));
    }
    if ((t & 31) == 0) { atomicMaxF(&sgm[0], ms); atomicMaxF(&sgm[1], md); }
    __syncthreads();
    if (t < 2) atomicMaxF(&g_gm3[t], sgm[t]);
}

// ---------------- bucket aggregation ----------------------------------------
// Layer 1: F=128, H=4. One warp per dst node, two-phase (f32 weights).
__global__ void __launch_bounds__(256) k_agg1(const float* __restrict__ b) {
    __shared__ float sew[8][4 * CAP];   // 16 KB: per-warp transposed edge weights
    int wid = threadIdx.x >> 5, lane = threadIdx.x & 31;
    int n = blockIdx.x * 8 + wid;
    if (n >= NN) return;
    float* sew_w = sew[wid];

    float4 gs = *(const float4*)&g_gm1[0];
    float4 gd = *(const float4*)&g_gm1[4];
    float nm0 = -lrelu_b(gs.x + gd.x) * LOG2E;
    float nm1 = -lrelu_b(gs.y + gd.y) * LOG2E;
    float nm2 = -lrelu_b(gs.z + gd.z) * LOG2E;
    float nm3 = -lrelu_b(gs.w + gd.w) * LOG2E;
    float4 ad4 = *(const float4*)&g_adst[n * 4];

    const int* eb = &g_eb[(size_t)n * CAP];
    int cnt = min(g_cnt[n], CAP);

    // phase 1: per-edge weights (once) + per-head denominator partials
    float d0 = 0.f, d1 = 0.f, d2 = 0.f, d3 = 0.f;
    for (int j = lane; j < cnt; j += 32) {
        int s = __ldg(&eb[j]);
        float4 a4 = *(const float4*)&g_asrc[s * 4];
        float e0 = eexp(lrelu_b(a4.x + ad4.x), nm0);
        float e1 = eexp(lrelu_b(a4.y + ad4.y), nm1);
        float e2 = eexp(lrelu_b(a4.z + ad4.z), nm2);
        float e3 = eexp(lrelu_b(a4.w + ad4.w), nm3);
        sew_w[j]           = e0;
        sew_w[CAP + j]     = e1;
        sew_w[2 * CAP + j] = e2;
        sew_w[3 * CAP + j] = e3;
        d0 += e0; d1 += e1; d2 += e2; d3 += e3;
    }
#pragma unroll
    for (int off = 16; off >= 1; off >>= 1) {
        d0 += __shfl_xor_sync(0xffffffffu, d0, off);
        d1 += __shfl_xor_sync(0xffffffffu, d1, off);
        d2 += __shfl_xor_sync(0xffffffffu, d2, off);
        d3 += __shfl_xor_sync(0xffffffffu, d3, off);
    }
    __syncwarp();

    // phase 2: feature accumulation, 8 edges/iter
    int h = lane >> 3, c0 = lane * 4;
    float ta = (h & 2) ? nm2 : nm0;
    float tb = (h & 2) ? nm3 : nm1;
    float nmm = (h & 1) ? tb : ta;
    float da = (h & 2) ? d2 : d0;
    float db = (h & 2) ? d3 : d1;
    float dh = (h & 1) ? db : da;
    float adn = g_adst[n * 4 + h];
    float es = eexp(lrelu_b(g_asrc[n * 4 + h] + adn), nmm);
    float4 hv = cvt4(*(const uint2*)&g_h16[(size_t)n * 128 + c0]);
    float ax = hv.x * es, ay = hv.y * es, az = hv.z * es, aw = hv.w * es;
    float den = dh + es;
    const float* ep = sew_w + h * CAP;
    int j = 0;
    for (; j + 8 <= cnt; j += 8) {
        int4 sA = *(const int4*)(eb + j);
        int4 sB = *(const int4*)(eb + j + 4);
        float4 eA = *(const float4*)&ep[j];
        float4 eB = *(const float4*)&ep[j + 4];
        uint2 u0 = *(const uint2*)&g_h16[(size_t)sA.x * 128 + c0];
        uint2 u1 = *(const uint2*)&g_h16[(size_t)sA.y * 128 + c0];
        uint2 u2 = *(const uint2*)&g_h16[(size_t)sA.z * 128 + c0];
        uint2 u3 = *(const uint2*)&g_h16[(size_t)sA.w * 128 + c0];
        uint2 u4 = *(const uint2*)&g_h16[(size_t)sB.x * 128 + c0];
        uint2 u5 = *(const uint2*)&g_h16[(size_t)sB.y * 128 + c0];
        uint2 u6 = *(const uint2*)&g_h16[(size_t)sB.z * 128 + c0];
        uint2 u7 = *(const uint2*)&g_h16[(size_t)sB.w * 128 + c0];
        float4 h0 = cvt4(u0), h1 = cvt4(u1), h2 = cvt4(u2), h3 = cvt4(u3);
        ax += h0.x * eA.x + h1.x * eA.y + h2.x * eA.z + h3.x * eA.w;
        ay += h0.y * eA.x + h1.y * eA.y + h2.y * eA.z + h3.y * eA.w;
        az += h0.z * eA.x + h1.z * eA.y + h2.z * eA.z + h3.z * eA.w;
        aw += h0.w * eA.x + h1.w * eA.y + h2.w * eA.z + h3.w * eA.w;
        float4 h4 = cvt4(u4), h5 = cvt4(u5), h6 = cvt4(u6), h7 = cvt4(u7);
        ax += h4.x * eB.x + h5.x * eB.y + h6.x * eB.z + h7.x * eB.w;
        ay += h4.y * eB.x + h5.y * eB.y + h6.y * eB.z + h7.y * eB.w;
        az += h4.z * eB.x + h5.z * eB.y + h6.z * eB.z + h7.z * eB.w;
        aw += h4.w * eB.x + h5.w * eB.y + h6.w * eB.z + h7.w * eB.w;
    }
    for (; j < cnt; j++) {
        int s0 = eb[j];
        float e0 = ep[j];
        float4 h0 = cvt4(*(const uint2*)&g_h16[(size_t)s0 * 128 + c0]);
        ax += h0.x * e0; ay += h0.y * e0; az += h0.z * e0; aw += h0.w * e0;
    }
    float inv = __frcp_rn(den);
    float4 bv = *(const float4*)&b[c0];
    float vx = elu_f(ax * inv + bv.x);
    float vy = elu_f(ay * inv + bv.y);
    float vz = elu_f(az * inv + bv.z);
    float vw = elu_f(aw * inv + bv.w);
    __half2 p0 = __float22half2_rn(make_float2(vx, vy));
    __half2 p1 = __float22half2_rn(make_float2(vz, vw));
    uint2 st;
    st.x = *(uint32_t*)&p0; st.y = *(uint32_t*)&p1;
    *(uint2*)&g_agg16[(size_t)n * 128 + c0] = st;
}

// Layer 2: F=32, H=2. 8 lanes per dst node (round-10 proven form).
__global__ void __launch_bounds__(256) k_agg2(const float* __restrict__ b) {
    int gi = blockIdx.x * blockDim.x + threadIdx.x;
    int n = gi >> 3, jl = gi & 7;
    if (n >= NN) return;
    int h = jl >> 2, c0 = jl * 4;
    float m = lrelu(g_gm2[h] + g_gm2[2 + h]);
    float nmm = -m * LOG2E;
    float adn = g_adst[n * 2 + h];
    float es = eexp(lrelu_b(g_asrc[n * 2 + h] + adn), nmm);
    float4 hv = cvt4(*(const uint2*)&g_h16[n * 32 + c0]);
    float ax = hv.x * es, ay = hv.y * es, az = hv.z * es, aw = hv.w * es;
    float den = es;
    const int* eb = &g_eb[(size_t)n * CAP];
    int cnt = min(g_cnt[n], CAP);
    int j = 0;
    for (; j + 4 <= cnt; j += 4) {
        int4 s4 = *(const int4*)(eb + j);
        float a0 = g_asrc[s4.x * 2 + h];
        float a1 = g_asrc[s4.y * 2 + h];
        float a2 = g_asrc[s4.z * 2 + h];
        float a3 = g_asrc[s4.w * 2 + h];
        uint2 u0 = *(const uint2*)&g_h16[s4.x * 32 + c0];
        uint2 u1 = *(const uint2*)&g_h16[s4.y * 32 + c0];
        uint2 u2 = *(const uint2*)&g_h16[s4.z * 32 + c0];
        uint2 u3 = *(const uint2*)&g_h16[s4.w * 32 + c0];
        float e0 = eexp(lrelu_b(a0 + adn), nmm);
        float e1 = eexp(lrelu_b(a1 + adn), nmm);
        float e2 = eexp(lrelu_b(a2 + adn), nmm);
        float e3 = eexp(lrelu_b(a3 + adn), nmm);
        float4 h0 = cvt4(u0), h1 = cvt4(u1), h2 = cvt4(u2), h3 = cvt4(u3);
        ax += h0.x * e0 + h1.x * e1 + h2.x * e2 + h3.x * e3;
        ay += h0.y * e0 + h1.y * e1 + h2.y * e2 + h3.y * e3;
        az += h0.z * e0 + h1.z * e1 + h2.z * e2 + h3.z * e3;
        aw += h0.w * e0 + h1.w * e1 + h2.w * e2 + h3.w * e3;
        den += (e0 + e1) + (e2 + e3);
    }
    for (; j < cnt; j++) {
        int s0 = eb[j];
        float a0 = g_asrc[s0 * 2 + h];
        uint2 u0 = *(const uint2*)&g_h16[s0 * 32 + c0];
        float e0 = eexp(lrelu_b(a0 + adn), nmm);
        float4 h0 = cvt4(u0);
        ax += h0.x * e0; ay += h0.y * e0; az += h0.z * e0; aw += h0.w * e0;
        den += e0;
    }
    float inv = __frcp_rn(den);
    float4 bv = *(const float4*)&b[c0];
    float vx = elu_f(ax * inv + bv.x);
    float vy = elu_f(ay * inv + bv.y);
    float vz = elu_f(az * inv + bv.z);
    float vw = elu_f(aw * inv + bv.w);
    *(float4*)&g_agg2[n * 32 + c0] = make_float4(vx, vy, vz, vw);
}

// Layer 3: F=2, H=1. One thread per dst node + fused log-softmax.
__global__ void k_agg3(const float* __restrict__ b3, float* __restrict__ out) {
    int n = blockIdx.x * blockDim.x + threadIdx.x;
    if (n >= NN) return;
    float m = lrelu(g_gm3[0] + g_gm3[1]);
    float nmm = -m * LOG2E;
    float adn = g_adst[n];
    float es = eexp(lrelu_b(g_asrc[n] + adn), nmm);
    float2 hv = *(const float2*)&g_h[2 * n];
    float a0 = hv.x * es, a1 = hv.y * es, den = es;
    const int* eb = &g_eb[(size_t)n * CAP];
    int cnt = min(g_cnt[n], CAP);
    int j = 0;
    for (; j + 4 <= cnt; j += 4) {
        int4 s4 = *(const int4*)(eb + j);
        float t0 = g_asrc[s4.x], t1 = g_asrc[s4.y];
        float t2 = g_asrc[s4.z], t3 = g_asrc[s4.w];
        float2 h0 = *(const float2*)&g_h[2 * s4.x];
        float2 h1 = *(const float2*)&g_h[2 * s4.y];
        float2 h2 = *(const float2*)&g_h[2 * s4.z];
        float2 h3 = *(const float2*)&g_h[2 * s4.w];
        float e0 = eexp(lrelu_b(t0 + adn), nmm);
        float e1 = eexp(lrelu_b(t1 + adn), nmm);
        float e2 = eexp(lrelu_b(t2 + adn), nmm);
        float e3 = eexp(lrelu_b(t3 + adn), nmm);
        a0 += h0.x * e0 + h1.x * e1 + h2.x * e2 + h3.x * e3;
        a1 += h0.y * e0 + h1.y * e1 + h2.y * e2 + h3.y * e3;
        den += (e0 + e1) + (e2 + e3);
    }
    for (; j < cnt; j++) {
        int s0 = eb[j];
        float t0 = g_asrc[s0];
        float2 h0 = *(const float2*)&g_h[2 * s0];
        float e0 = eexp(lrelu_b(t0 + adn), nmm);
        a0 += h0.x * e0; a1 += h0.y * e0; den += e0;
    }
    float inv = __frcp_rn(den);
    float z0 = a0 * inv + b3[0];
    float z1 = a1 * inv + b3[1];
    float mx = fmaxf(z0, z1);
    float lse = mx + logf(expf(z0 - mx) + expf(z1 - mx));
    out[2 * n] = z0 - lse;
    out[2 * n + 1] = z1 - lse;
}

// ---------------- host ------------------------------------------------------
extern "C" void kernel_launch(void* const* d_in, const int* in_sizes, int n_in,
                              void* d_out, int out_size) {
    const float* x   = (const float*)d_in[0];
    const int*   ei  = (const int*)d_in[1];
    const float* W1  = (const float*)d_in[2];
    const float* as1 = (const float*)d_in[3];
    const float* ad1 = (const float*)d_in[4];
    const float* b1  = (const float*)d_in[5];
    const float* W2  = (const float*)d_in[6];
    const float* as2 = (const float*)d_in[7];
    const float* ad2 = (const float*)d_in[8];
    const float* b2  = (const float*)d_in[9];
    const float* W3  = (const float*)d_in[10];
    const float* as3 = (const float*)d_in[11];
    const float* ad3 = (const float*)d_in[12];
    const float* b3  = (const float*)d_in[13];
    float* out = (float*)d_out;

    __half* p_agg16;
    float* p_agg2;
    cudaGetSymbolAddress((void**)&p_agg16, g_agg16);
    cudaGetSymbolAddress((void**)&p_agg2, g_agg2);

    const int TB = 256;
    const size_t SMEM1 = (size_t)(64 * XS_STRIDE + 128 * WS_STRIDE) * 4;
    const size_t SMEM2 = (size_t)(128 * XS2_STRIDE + 128 * WS2_STRIDE) * 4;

    static cudaStream_t s1 = nullptr;
    static cudaEvent_t ev0 = nullptr, ev1 = nullptr;
    if (!s1) {
        cudaFuncSetAttribute(k_gemm1_mma, cudaFuncAttributeMaxDynamicSharedMemorySize,
                             (int)SMEM1);
        cudaFuncSetAttribute(k_gemm2_mma, cudaFuncAttributeMaxDynamicSharedMemorySize,
                             (int)SMEM2);
        cudaStreamCreateWithFlags(&s1, cudaStreamNonBlocking);
        cudaEventCreateWithFlags(&ev0, cudaEventDisableTiming);
        cudaEventCreateWithFlags(&ev1, cudaEventDisableTiming);
    }

    // ---- setup, then fork: scatter (s1) || gemm1 (legacy) ----
    k_setup<<<NB_SETUP, 1024>>>(ei);
    cudaEventRecord(ev0, 0);
    cudaStreamWaitEvent(s1, ev0, 0);
    k_scatter<<<(NE + TB * 8 - 1) / (TB * 8), TB, 0, s1>>>(ei);
    cudaEventRecord(ev1, s1);

    k_gemm1_mma<<<(NN + 63) / 64, TB, SMEM1>>>(x, W1, as1, ad1);

    // join: agg1 needs both gemm1 (legacy) and scatter (s1)
    cudaStreamWaitEvent(0, ev1, 0);

    // ---- layer 1 (H=4, O=32, F=128) ----
    k_agg1<<<(NN + 7) / 8, TB>>>(b1);

    // ---- layer 2 (H=2, O=16, F=32) ----
    k_gemm2_mma<<<(NN + 127) / 128, TB, SMEM2>>>(p_agg16, W2, as2, ad2);
    k_agg2<<<(NN * 8 + TB - 1) / TB, TB>>>(b2);

    // ---- layer 3 (H=1, O=2, F=2) ----
    k_gemm3<<<(NN + TB - 1) / TB, TB>>>(p_agg2, W3, as3, ad3);
    k_agg3<<<(NN + TB - 1) / TB, TB>>>(b3, out);
}